// round 1
// baseline (speedup 1.0000x reference)
#include <cuda_runtime.h>
#include <math.h>

#define NU 50000
#define NP 50000
#define NEMAX 400000
#define IND 128
#define HID 64
#define NH 4
#define HH 256   // HEADS*HID
#define OUTD 64

// ---------------- scratch (static device globals; no allocation) ----------------
__device__ float g_hu[NU * HID];
__device__ float g_hp[NP * HID];
__device__ float g_hs[3][NU * HH];      // hu@lin_u2u, hp@lin_p2u, hu@lin_u2p
__device__ float g_a[6][NU * NH];       // folded attention scalars
__device__ float g_wf[6][HID * NH];     // folded lin@att^T
__device__ float g_e[NEMAX * NH];       // edge logits / scratch
__device__ int   g_cnt[NU];
__device__ int   g_rp[NU + 1];
__device__ int   g_cur[NU];
__device__ int   g_perm[NEMAX];
__device__ float g_out[2][NU * HH];     // conv outputs: [0]=user (summed), [1]=post

__device__ __forceinline__ float lrelu(float x) {
    return fmaxf(x, 0.f) + 0.2f * fminf(x, 0.f);
}
__device__ __forceinline__ float elu(float x) {
    return x > 0.f ? x : expm1f(x);
}

// ---------------- fold lin @ att^T into [64,4] per (edge-type, src/dst) ----------------
__global__ void k_fold(const float* __restrict__ l0, const float* __restrict__ l1,
                       const float* __restrict__ l2,
                       const float* __restrict__ a0, const float* __restrict__ a1,
                       const float* __restrict__ a2, const float* __restrict__ a3,
                       const float* __restrict__ a4, const float* __restrict__ a5) {
    int combo = blockIdx.x;  // 0..5
    const float* lin = combo < 2 ? l0 : (combo < 4 ? l1 : l2);
    const float* att = combo == 0 ? a0 : combo == 1 ? a1 : combo == 2 ? a2
                     : combo == 3 ? a3 : combo == 4 ? a4 : a5;
    int t = threadIdx.x;          // 256 threads = 64 cin x 4 heads
    int cin = t >> 2, h = t & 3;
    const float* lr = lin + cin * HH + h * HID;
    const float* ar = att + h * HID;
    float s = 0.f;
#pragma unroll 8
    for (int c = 0; c < HID; ++c) s += lr[c] * ar[c];
    g_wf[combo][cin * NH + h] = s;
}

// ---------------- projection: [100000,128] @ [128,64] + b  ->  g_hu / g_hp ----------------
__global__ void __launch_bounds__(256) k_proj(const float* __restrict__ xu,
                                              const float* __restrict__ xp,
                                              const float* __restrict__ W,
                                              const float* __restrict__ b) {
    __shared__ float As[32][132];   // [k][m], padded
    __shared__ float Bs[32][68];    // [k][n], padded
    int tid = threadIdx.x;
    int r0 = blockIdx.x * 128;
    int tx = tid & 15, ty = tid >> 4;
    float acc[8][4] = {};

    for (int kk = 0; kk < IND; kk += 32) {
        // A tile 128x32 = 1024 float4, 4 per thread
#pragma unroll
        for (int i = 0; i < 4; ++i) {
            int f4 = i * 256 + tid;
            int row = f4 >> 3;      // 8 f4 per row
            int kc4 = f4 & 7;
            int gr = r0 + row;
            float4 v = make_float4(0.f, 0.f, 0.f, 0.f);
            if (gr < NU + NP) {
                const float* srcp = gr < NU ? xu + (size_t)gr * IND
                                            : xp + (size_t)(gr - NU) * IND;
                v = *(const float4*)(srcp + kk + kc4 * 4);
            }
            As[kc4 * 4 + 0][row] = v.x; As[kc4 * 4 + 1][row] = v.y;
            As[kc4 * 4 + 2][row] = v.z; As[kc4 * 4 + 3][row] = v.w;
        }
        // B tile 32x64 = 512 float4, 2 per thread
#pragma unroll
        for (int i = 0; i < 2; ++i) {
            int f4 = i * 256 + tid;
            int k = f4 >> 4, c4 = f4 & 15;
            *(float4*)&Bs[k][c4 * 4] = *(const float4*)(W + (kk + k) * 64 + c4 * 4);
        }
        __syncthreads();
#pragma unroll
        for (int k = 0; k < 32; ++k) {
            float4 a0 = *(float4*)&As[k][ty * 8];
            float4 a1 = *(float4*)&As[k][ty * 8 + 4];
            float4 bv = *(float4*)&Bs[k][tx * 4];
            float am[8] = {a0.x, a0.y, a0.z, a0.w, a1.x, a1.y, a1.z, a1.w};
            float bm[4] = {bv.x, bv.y, bv.z, bv.w};
#pragma unroll
            for (int i = 0; i < 8; ++i)
#pragma unroll
                for (int j = 0; j < 4; ++j) acc[i][j] += am[i] * bm[j];
        }
        __syncthreads();
    }
    float4 bb = *(const float4*)(b + tx * 4);
#pragma unroll
    for (int i = 0; i < 8; ++i) {
        int gr = r0 + ty * 8 + i;
        if (gr >= NU + NP) continue;
        float4 o = make_float4(acc[i][0] + bb.x, acc[i][1] + bb.y,
                               acc[i][2] + bb.z, acc[i][3] + bb.w);
        float* dst = gr < NU ? g_hu + (size_t)gr * HID
                             : g_hp + (size_t)(gr - NU) * HID;
        *(float4*)(dst + tx * 4) = o;
    }
}

// ---------------- attention scalars: a[z] = H @ wf[z],  [50000,64]@[64,4] ----------------
__global__ void k_att() {
    int z = blockIdx.y;
    __shared__ float wf[HID * NH];
    wf[threadIdx.x] = g_wf[z][threadIdx.x];   // blockDim = 256 = HID*NH
    __syncthreads();
    int node = blockIdx.x * 256 + threadIdx.x;
    if (node >= NU) return;
    const float* H = (z == 2 || z == 5) ? g_hp : g_hu;
    const float* hr = H + (size_t)node * HID;
    float a0 = 0.f, a1 = 0.f, a2 = 0.f, a3 = 0.f;
#pragma unroll
    for (int c = 0; c < HID; c += 4) {
        float4 h4 = *(const float4*)(hr + c);
        a0 += h4.x * wf[(c + 0) * 4 + 0] + h4.y * wf[(c + 1) * 4 + 0]
            + h4.z * wf[(c + 2) * 4 + 0] + h4.w * wf[(c + 3) * 4 + 0];
        a1 += h4.x * wf[(c + 0) * 4 + 1] + h4.y * wf[(c + 1) * 4 + 1]
            + h4.z * wf[(c + 2) * 4 + 1] + h4.w * wf[(c + 3) * 4 + 1];
        a2 += h4.x * wf[(c + 0) * 4 + 2] + h4.y * wf[(c + 1) * 4 + 2]
            + h4.z * wf[(c + 2) * 4 + 2] + h4.w * wf[(c + 3) * 4 + 2];
        a3 += h4.x * wf[(c + 0) * 4 + 3] + h4.y * wf[(c + 1) * 4 + 3]
            + h4.z * wf[(c + 2) * 4 + 3] + h4.w * wf[(c + 3) * 4 + 3];
    }
    *(float4*)&g_a[z][node * 4] = make_float4(a0, a1, a2, a3);
}

// ---------------- message GEMMs: g_hs[z] = A @ lin_z,  [50000,64]@[64,256] ----------------
__global__ void __launch_bounds__(256) k_lin(const float* __restrict__ l0,
                                             const float* __restrict__ l1,
                                             const float* __restrict__ l2) {
    __shared__ float As[32][132];   // [k][m]
    __shared__ float Bs[32][132];   // [k][n]
    int z = blockIdx.z;
    const float* A = (z == 1) ? g_hp : g_hu;
    const float* B = z == 0 ? l0 : (z == 1 ? l1 : l2);
    float* C = g_hs[z];
    int tid = threadIdx.x;
    int r0 = blockIdx.x * 128;
    int n0 = blockIdx.y * 128;
    int tx = tid & 15, ty = tid >> 4;
    float acc[8][8] = {};

    for (int kk = 0; kk < HID; kk += 32) {
        // A tile 128x32 = 1024 f4, 4/thread
#pragma unroll
        for (int i = 0; i < 4; ++i) {
            int f4 = i * 256 + tid;
            int row = f4 >> 3, kc4 = f4 & 7;
            int gr = r0 + row;
            float4 v = make_float4(0.f, 0.f, 0.f, 0.f);
            if (gr < NU) v = *(const float4*)(A + (size_t)gr * HID + kk + kc4 * 4);
            As[kc4 * 4 + 0][row] = v.x; As[kc4 * 4 + 1][row] = v.y;
            As[kc4 * 4 + 2][row] = v.z; As[kc4 * 4 + 3][row] = v.w;
        }
        // B tile 32x128 = 1024 f4, 4/thread
#pragma unroll
        for (int i = 0; i < 4; ++i) {
            int f4 = i * 256 + tid;
            int k = f4 >> 5, c4 = f4 & 31;
            *(float4*)&Bs[k][c4 * 4] = *(const float4*)(B + (kk + k) * HH + n0 + c4 * 4);
        }
        __syncthreads();
#pragma unroll
        for (int k = 0; k < 32; ++k) {
            float4 a0 = *(float4*)&As[k][ty * 8];
            float4 a1 = *(float4*)&As[k][ty * 8 + 4];
            float4 b0 = *(float4*)&Bs[k][tx * 8];
            float4 b1 = *(float4*)&Bs[k][tx * 8 + 4];
            float am[8] = {a0.x, a0.y, a0.z, a0.w, a1.x, a1.y, a1.z, a1.w};
            float bm[8] = {b0.x, b0.y, b0.z, b0.w, b1.x, b1.y, b1.z, b1.w};
#pragma unroll
            for (int i = 0; i < 8; ++i)
#pragma unroll
                for (int j = 0; j < 8; ++j) acc[i][j] += am[i] * bm[j];
        }
        __syncthreads();
    }
#pragma unroll
    for (int i = 0; i < 8; ++i) {
        int gr = r0 + ty * 8 + i;
        if (gr >= NU) continue;
        *(float4*)(C + (size_t)gr * HH + n0 + tx * 8) =
            make_float4(acc[i][0], acc[i][1], acc[i][2], acc[i][3]);
        *(float4*)(C + (size_t)gr * HH + n0 + tx * 8 + 4) =
            make_float4(acc[i][4], acc[i][5], acc[i][6], acc[i][7]);
    }
}

// ---------------- CSR build ----------------
__global__ void k_zero_cnt() {
    int i = blockIdx.x * 256 + threadIdx.x;
    if (i < NU) g_cnt[i] = 0;
}
__global__ void k_hist(const int* __restrict__ dst, int E) {
    int e = blockIdx.x * 256 + threadIdx.x;
    if (e < E) atomicAdd(&g_cnt[dst[e]], 1);
}
__global__ void k_scan() {
    __shared__ int sd[1024];
    int tid = threadIdx.x;
    int carry = 0;
    for (int base = 0; base < NU; base += 1024) {
        int i = base + tid;
        int v = (i < NU) ? g_cnt[i] : 0;
        sd[tid] = v;
        __syncthreads();
        for (int o = 1; o < 1024; o <<= 1) {
            int t = (tid >= o) ? sd[tid - o] : 0;
            __syncthreads();
            sd[tid] += t;
            __syncthreads();
        }
        int incl = sd[tid];
        if (i < NU) {
            int ex = carry + incl - v;
            g_rp[i] = ex;
            g_cur[i] = ex;
        }
        carry += sd[1023];
        __syncthreads();
    }
    if (tid == 0) g_rp[NU] = carry;
}
__global__ void k_scatter(const int* __restrict__ dst, int E) {
    int e = blockIdx.x * 256 + threadIdx.x;
    if (e < E) {
        int p = atomicAdd(&g_cur[dst[e]], 1);
        g_perm[p] = e;
    }
}

// ---------------- edge logits ----------------
__global__ void k_logits(const int* __restrict__ src, const int* __restrict__ dst,
                         int asIdx, int adIdx, int E) {
    int e = blockIdx.x * 256 + threadIdx.x;
    if (e >= E) return;
    float4 s4 = *(const float4*)&g_a[asIdx][src[e] * 4];
    float4 d4 = *(const float4*)&g_a[adIdx][dst[e] * 4];
    float4 v = make_float4(lrelu(s4.x + d4.x), lrelu(s4.y + d4.y),
                           lrelu(s4.z + d4.z), lrelu(s4.w + d4.w));
    *(float4*)&g_e[e * 4] = v;
}

// ---------------- warp-per-dst softmax + weighted aggregation ----------------
__global__ void __launch_bounds__(256) k_gat(const int* __restrict__ src,
                                             int hsIdx, int outIdx, int accum) {
    int d = (blockIdx.x * 256 + threadIdx.x) >> 5;
    int lane = threadIdx.x & 31;
    if (d >= NU) return;
    int beg = g_rp[d], end = g_rp[d + 1];
    const float* hs = g_hs[hsIdx];

    // phase A: per-head max
    float m0 = -INFINITY, m1 = -INFINITY, m2 = -INFINITY, m3 = -INFINITY;
    for (int j = beg + lane; j < end; j += 32) {
        int e = g_perm[j];
        float4 ev = *(const float4*)&g_e[e * 4];
        m0 = fmaxf(m0, ev.x); m1 = fmaxf(m1, ev.y);
        m2 = fmaxf(m2, ev.z); m3 = fmaxf(m3, ev.w);
    }
#pragma unroll
    for (int o = 16; o; o >>= 1) {
        m0 = fmaxf(m0, __shfl_xor_sync(0xffffffffu, m0, o));
        m1 = fmaxf(m1, __shfl_xor_sync(0xffffffffu, m1, o));
        m2 = fmaxf(m2, __shfl_xor_sync(0xffffffffu, m2, o));
        m3 = fmaxf(m3, __shfl_xor_sync(0xffffffffu, m3, o));
    }
    // phase B: per-head exp-sum
    float s0 = 0.f, s1 = 0.f, s2 = 0.f, s3 = 0.f;
    for (int j = beg + lane; j < end; j += 32) {
        int e = g_perm[j];
        float4 ev = *(const float4*)&g_e[e * 4];
        s0 += __expf(ev.x - m0); s1 += __expf(ev.y - m1);
        s2 += __expf(ev.z - m2); s3 += __expf(ev.w - m3);
    }
#pragma unroll
    for (int o = 16; o; o >>= 1) {
        s0 += __shfl_xor_sync(0xffffffffu, s0, o);
        s1 += __shfl_xor_sync(0xffffffffu, s1, o);
        s2 += __shfl_xor_sync(0xffffffffu, s2, o);
        s3 += __shfl_xor_sync(0xffffffffu, s3, o);
    }
    float i0 = 1.f / (s0 + 1e-16f), i1 = 1.f / (s1 + 1e-16f);
    float i2 = 1.f / (s2 + 1e-16f), i3 = 1.f / (s3 + 1e-16f);

    // phase C: weighted aggregate; lane covers channels [lane*8, lane*8+8)
    int h = lane >> 3;
    float mh = h == 0 ? m0 : h == 1 ? m1 : h == 2 ? m2 : m3;
    float ih = h == 0 ? i0 : h == 1 ? i1 : h == 2 ? i2 : i3;
    float4 acc0 = make_float4(0.f, 0.f, 0.f, 0.f);
    float4 acc1 = make_float4(0.f, 0.f, 0.f, 0.f);
    int coff = lane * 8;
    for (int j = beg; j < end; ++j) {
        int e = g_perm[j];
        int sr = src[e];
        float al = __expf(g_e[e * 4 + h] - mh) * ih;
        const float4* p = (const float4*)&hs[(size_t)sr * HH + coff];
        float4 v0 = p[0], v1 = p[1];
        acc0.x += al * v0.x; acc0.y += al * v0.y;
        acc0.z += al * v0.z; acc0.w += al * v0.w;
        acc1.x += al * v1.x; acc1.y += al * v1.y;
        acc1.z += al * v1.z; acc1.w += al * v1.w;
    }
    float* op = &g_out[outIdx][(size_t)d * HH + coff];
    if (accum) {
        float4 p0 = *(float4*)op, p1 = *(float4*)(op + 4);
        acc0.x += p0.x; acc0.y += p0.y; acc0.z += p0.z; acc0.w += p0.w;
        acc1.x += p1.x; acc1.y += p1.y; acc1.z += p1.z; acc1.w += p1.w;
    }
    *(float4*)op = acc0;
    *(float4*)(op + 4) = acc1;
}

// ---------------- post output: elu(conv + bias) ----------------
__global__ void k_elu_post(const float* __restrict__ bias, float* __restrict__ dout) {
    int i = blockIdx.x * 256 + threadIdx.x;
    if (i >= NP * HH) return;
    float v = g_out[1][i] + bias[i & 255];
    dout[i] = elu(v);
}

// ---------------- user output: elu(conv+b1+b2) @ W_out + b_out ----------------
__global__ void __launch_bounds__(256) k_gout(const float* __restrict__ W,
                                              const float* __restrict__ bo,
                                              const float* __restrict__ b1,
                                              const float* __restrict__ b2,
                                              float* __restrict__ dout) {
    __shared__ float As[32][132];
    __shared__ float Bs[32][68];
    int tid = threadIdx.x;
    int r0 = blockIdx.x * 128;
    int tx = tid & 15, ty = tid >> 4;
    float acc[8][4] = {};

    for (int kk = 0; kk < HH; kk += 32) {
        // A tile 128x32 with fused bias + elu
#pragma unroll
        for (int i = 0; i < 4; ++i) {
            int f4 = i * 256 + tid;
            int row = f4 >> 3, kc4 = f4 & 7;
            int gr = r0 + row;
            float4 v = make_float4(0.f, 0.f, 0.f, 0.f);
            if (gr < NU) {
                v = *(const float4*)&g_out[0][(size_t)gr * HH + kk + kc4 * 4];
                float4 bb1 = *(const float4*)(b1 + kk + kc4 * 4);
                float4 bb2 = *(const float4*)(b2 + kk + kc4 * 4);
                v.x = elu(v.x + bb1.x + bb2.x);
                v.y = elu(v.y + bb1.y + bb2.y);
                v.z = elu(v.z + bb1.z + bb2.z);
                v.w = elu(v.w + bb1.w + bb2.w);
            }
            As[kc4 * 4 + 0][row] = v.x; As[kc4 * 4 + 1][row] = v.y;
            As[kc4 * 4 + 2][row] = v.z; As[kc4 * 4 + 3][row] = v.w;
        }
        // B tile 32x64
#pragma unroll
        for (int i = 0; i < 2; ++i) {
            int f4 = i * 256 + tid;
            int k = f4 >> 4, c4 = f4 & 15;
            *(float4*)&Bs[k][c4 * 4] = *(const float4*)(W + (kk + k) * OUTD + c4 * 4);
        }
        __syncthreads();
#pragma unroll
        for (int k = 0; k < 32; ++k) {
            float4 a0 = *(float4*)&As[k][ty * 8];
            float4 a1 = *(float4*)&As[k][ty * 8 + 4];
            float4 bv = *(float4*)&Bs[k][tx * 4];
            float am[8] = {a0.x, a0.y, a0.z, a0.w, a1.x, a1.y, a1.z, a1.w};
            float bm[4] = {bv.x, bv.y, bv.z, bv.w};
#pragma unroll
            for (int i = 0; i < 8; ++i)
#pragma unroll
                for (int j = 0; j < 4; ++j) acc[i][j] += am[i] * bm[j];
        }
        __syncthreads();
    }
    float4 bb = *(const float4*)(bo + tx * 4);
#pragma unroll
    for (int i = 0; i < 8; ++i) {
        int gr = r0 + ty * 8 + i;
        if (gr >= NU) continue;
        *(float4*)(dout + (size_t)gr * OUTD + tx * 4) =
            make_float4(acc[i][0] + bb.x, acc[i][1] + bb.y,
                        acc[i][2] + bb.z, acc[i][3] + bb.w);
    }
}

// ---------------- launch ----------------
extern "C" void kernel_launch(void* const* d_in, const int* in_sizes, int n_in,
                              void* d_out, int out_size) {
    const float* x_user     = (const float*)d_in[0];
    const float* x_post     = (const float*)d_in[1];
    const int*   src_u2u    = (const int*)d_in[2];
    const int*   dst_u2u    = (const int*)d_in[3];
    const int*   src_p2u    = (const int*)d_in[4];
    const int*   dst_p2u    = (const int*)d_in[5];
    const int*   src_u2p    = (const int*)d_in[6];
    const int*   dst_u2p    = (const int*)d_in[7];
    const float* W_proj     = (const float*)d_in[8];
    const float* b_proj     = (const float*)d_in[9];
    const float* lin_u2u    = (const float*)d_in[10];
    const float* att_s_u2u  = (const float*)d_in[11];
    const float* att_d_u2u  = (const float*)d_in[12];
    const float* bias_u2u   = (const float*)d_in[13];
    const float* lin_p2u    = (const float*)d_in[14];
    const float* att_s_p2u  = (const float*)d_in[15];
    const float* att_d_p2u  = (const float*)d_in[16];
    const float* bias_p2u   = (const float*)d_in[17];
    const float* lin_u2p    = (const float*)d_in[18];
    const float* att_s_u2p  = (const float*)d_in[19];
    const float* att_d_u2p  = (const float*)d_in[20];
    const float* bias_u2p   = (const float*)d_in[21];
    const float* W_out      = (const float*)d_in[22];
    const float* b_out      = (const float*)d_in[23];
    float* out = (float*)d_out;
    int E = in_sizes[2];

    k_fold<<<6, 256>>>(lin_u2u, lin_p2u, lin_u2p,
                       att_s_u2u, att_d_u2u, att_s_p2u, att_d_p2u, att_s_u2p, att_d_u2p);
    k_proj<<<(NU + NP + 127) / 128, 256>>>(x_user, x_post, W_proj, b_proj);
    k_att<<<dim3((NU + 255) / 256, 6), 256>>>();
    k_lin<<<dim3((NU + 127) / 128, 2, 3), 256>>>(lin_u2u, lin_p2u, lin_u2p);

    const int* srcs[3] = {src_u2u, src_p2u, src_u2p};
    const int* dsts[3] = {dst_u2u, dst_p2u, dst_u2p};
    int asI[3] = {0, 2, 4}, adI[3] = {1, 3, 5};
    int hsI[3] = {0, 1, 2}, outI[3] = {0, 0, 1}, accF[3] = {0, 1, 0};
    int gE = (E + 255) / 256;

    for (int t = 0; t < 3; ++t) {
        k_zero_cnt<<<(NU + 255) / 256, 256>>>();
        k_hist<<<gE, 256>>>(dsts[t], E);
        k_scan<<<1, 1024>>>();
        k_scatter<<<gE, 256>>>(dsts[t], E);
        k_logits<<<gE, 256>>>(srcs[t], dsts[t], asI[t], adI[t], E);
        k_gat<<<(NU * 32 + 255) / 256, 256>>>(srcs[t], hsI[t], outI[t], accF[t]);
    }

    k_elu_post<<<(NP * HH + 255) / 256, 256>>>(bias_u2p, out + (size_t)NU * OUTD);
    k_gout<<<(NU + 127) / 128, 256>>>(W_out, b_out, bias_u2u, bias_p2u, out);
}

// round 2
// speedup vs baseline: 1.2919x; 1.2919x over previous
#include <cuda_runtime.h>
#include <math.h>

#define NU 50000
#define NP 50000
#define NEMAX 400000
#define IND 128
#define HID 64
#define NH 4
#define HH 256   // HEADS*HID
#define OUTD 64

// ---------------- scratch (static device globals; no allocation) ----------------
__device__ float  g_hu[NU * HID];
__device__ float  g_hp[NP * HID];
__device__ float  g_hs[3][NU * HH];      // hu@lin_u2u, hp@lin_p2u, hu@lin_u2p
__device__ float  g_a[6][NU * NH];       // folded attention scalars
__device__ float  g_wf[6][HID * NH];     // folded lin@att^T
__device__ float4 g_pe[3][NEMAX];        // permuted edge logits (CSR slot order)
__device__ int    g_psrc[3][NEMAX];      // permuted src (CSR slot order)
__device__ int    g_cnt3[3][NU];
__device__ int    g_rp3[3][NU + 1];
__device__ int    g_cur3[3][NU];
__device__ int    g_perm3[3][NEMAX];
__device__ float  g_outT[3][NU * HH];    // per-type conv outputs (0:u2u, 1:p2u, 2:u2p)

__device__ __forceinline__ float lrelu(float x) {
    return fmaxf(x, 0.f) + 0.2f * fminf(x, 0.f);
}
__device__ __forceinline__ float elu(float x) {
    return x > 0.f ? x : expm1f(x);
}

// ---------------- fold lin @ att^T into [64,4] per (edge-type, src/dst) ----------------
__global__ void k_fold(const float* __restrict__ l0, const float* __restrict__ l1,
                       const float* __restrict__ l2,
                       const float* __restrict__ a0, const float* __restrict__ a1,
                       const float* __restrict__ a2, const float* __restrict__ a3,
                       const float* __restrict__ a4, const float* __restrict__ a5) {
    int combo = blockIdx.x;  // 0..5
    const float* lin = combo < 2 ? l0 : (combo < 4 ? l1 : l2);
    const float* att = combo == 0 ? a0 : combo == 1 ? a1 : combo == 2 ? a2
                     : combo == 3 ? a3 : combo == 4 ? a4 : a5;
    int t = threadIdx.x;          // 256 threads = 64 cin x 4 heads
    int cin = t >> 2, h = t & 3;
    const float* lr = lin + cin * HH + h * HID;
    const float* ar = att + h * HID;
    float s = 0.f;
#pragma unroll 8
    for (int c = 0; c < HID; ++c) s += lr[c] * ar[c];
    g_wf[combo][cin * NH + h] = s;
}

// ---------------- projection: [100000,128] @ [128,64] + b  ->  g_hu / g_hp ----------------
__global__ void __launch_bounds__(256, 2) k_proj(const float* __restrict__ xu,
                                                 const float* __restrict__ xp,
                                                 const float* __restrict__ W,
                                                 const float* __restrict__ b) {
    __shared__ float As[32][132];   // [k][m], padded
    __shared__ float Bs[32][68];    // [k][n], padded
    int tid = threadIdx.x;
    int r0 = blockIdx.x * 128;
    int tx = tid & 15, ty = tid >> 4;
    float acc[8][4] = {};

    for (int kk = 0; kk < IND; kk += 32) {
#pragma unroll
        for (int i = 0; i < 4; ++i) {
            int f4 = i * 256 + tid;
            int row = f4 >> 3;
            int kc4 = f4 & 7;
            int gr = r0 + row;
            float4 v = make_float4(0.f, 0.f, 0.f, 0.f);
            if (gr < NU + NP) {
                const float* srcp = gr < NU ? xu + (size_t)gr * IND
                                            : xp + (size_t)(gr - NU) * IND;
                v = *(const float4*)(srcp + kk + kc4 * 4);
            }
            As[kc4 * 4 + 0][row] = v.x; As[kc4 * 4 + 1][row] = v.y;
            As[kc4 * 4 + 2][row] = v.z; As[kc4 * 4 + 3][row] = v.w;
        }
#pragma unroll
        for (int i = 0; i < 2; ++i) {
            int f4 = i * 256 + tid;
            int k = f4 >> 4, c4 = f4 & 15;
            *(float4*)&Bs[k][c4 * 4] = *(const float4*)(W + (kk + k) * 64 + c4 * 4);
        }
        __syncthreads();
#pragma unroll
        for (int k = 0; k < 32; ++k) {
            float4 a0 = *(float4*)&As[k][ty * 8];
            float4 a1 = *(float4*)&As[k][ty * 8 + 4];
            float4 bv = *(float4*)&Bs[k][tx * 4];
            float am[8] = {a0.x, a0.y, a0.z, a0.w, a1.x, a1.y, a1.z, a1.w};
            float bm[4] = {bv.x, bv.y, bv.z, bv.w};
#pragma unroll
            for (int i = 0; i < 8; ++i)
#pragma unroll
                for (int j = 0; j < 4; ++j) acc[i][j] += am[i] * bm[j];
        }
        __syncthreads();
    }
    float4 bb = *(const float4*)(b + tx * 4);
#pragma unroll
    for (int i = 0; i < 8; ++i) {
        int gr = r0 + ty * 8 + i;
        if (gr >= NU + NP) continue;
        float4 o = make_float4(acc[i][0] + bb.x, acc[i][1] + bb.y,
                               acc[i][2] + bb.z, acc[i][3] + bb.w);
        float* dst = gr < NU ? g_hu + (size_t)gr * HID
                             : g_hp + (size_t)(gr - NU) * HID;
        *(float4*)(dst + tx * 4) = o;
    }
}

// ---------------- attention scalars, H read once per node ----------------
// blockIdx.y==0: user nodes -> z {0,1,3,4};  blockIdx.y==1: post nodes -> z {2,5}
__global__ void k_att2() {
    int part = blockIdx.y;
    __shared__ float wf[4][HID * NH];
    int nz = part ? 2 : 4;
    int zsU[4] = {0, 1, 3, 4};
    int zsP[2] = {2, 5};
#pragma unroll
    for (int zi = 0; zi < 4; ++zi) {
        if (zi < nz) {
            int z = part ? zsP[zi] : zsU[zi];
            wf[zi][threadIdx.x] = g_wf[z][threadIdx.x];
        }
    }
    __syncthreads();
    int node = blockIdx.x * 256 + threadIdx.x;
    if (node >= NU) return;
    const float* hr = (part ? g_hp : g_hu) + (size_t)node * HID;
    float acc[4][4] = {};
#pragma unroll
    for (int c = 0; c < HID; c += 4) {
        float4 h4 = *(const float4*)(hr + c);
#pragma unroll
        for (int zi = 0; zi < 4; ++zi) {
            if (zi >= nz) break;
#pragma unroll
            for (int hh = 0; hh < 4; ++hh) {
                acc[zi][hh] += h4.x * wf[zi][(c + 0) * 4 + hh]
                             + h4.y * wf[zi][(c + 1) * 4 + hh]
                             + h4.z * wf[zi][(c + 2) * 4 + hh]
                             + h4.w * wf[zi][(c + 3) * 4 + hh];
            }
        }
    }
#pragma unroll
    for (int zi = 0; zi < 4; ++zi) {
        if (zi >= nz) break;
        int z = part ? zsP[zi] : zsU[zi];
        *(float4*)&g_a[z][node * 4] =
            make_float4(acc[zi][0], acc[zi][1], acc[zi][2], acc[zi][3]);
    }
}

// ---------------- message GEMMs: g_hs[z] = A @ lin_z,  [50000,64]@[64,256] ----------------
__global__ void __launch_bounds__(256, 2) k_lin(const float* __restrict__ l0,
                                                const float* __restrict__ l1,
                                                const float* __restrict__ l2) {
    __shared__ float As[32][132];   // [k][m]
    __shared__ float Bs[32][132];   // [k][n]
    int z = blockIdx.z;
    const float* A = (z == 1) ? g_hp : g_hu;
    const float* B = z == 0 ? l0 : (z == 1 ? l1 : l2);
    float* C = g_hs[z];
    int tid = threadIdx.x;
    int r0 = blockIdx.x * 128;
    int n0 = blockIdx.y * 128;
    int tx = tid & 15, ty = tid >> 4;
    float acc[8][8] = {};

    for (int kk = 0; kk < HID; kk += 32) {
#pragma unroll
        for (int i = 0; i < 4; ++i) {
            int f4 = i * 256 + tid;
            int row = f4 >> 3, kc4 = f4 & 7;
            int gr = r0 + row;
            float4 v = make_float4(0.f, 0.f, 0.f, 0.f);
            if (gr < NU) v = *(const float4*)(A + (size_t)gr * HID + kk + kc4 * 4);
            As[kc4 * 4 + 0][row] = v.x; As[kc4 * 4 + 1][row] = v.y;
            As[kc4 * 4 + 2][row] = v.z; As[kc4 * 4 + 3][row] = v.w;
        }
#pragma unroll
        for (int i = 0; i < 4; ++i) {
            int f4 = i * 256 + tid;
            int k = f4 >> 5, c4 = f4 & 31;
            *(float4*)&Bs[k][c4 * 4] = *(const float4*)(B + (kk + k) * HH + n0 + c4 * 4);
        }
        __syncthreads();
#pragma unroll
        for (int k = 0; k < 32; ++k) {
            float4 a0 = *(float4*)&As[k][ty * 8];
            float4 a1 = *(float4*)&As[k][ty * 8 + 4];
            float4 b0 = *(float4*)&Bs[k][tx * 8];
            float4 b1 = *(float4*)&Bs[k][tx * 8 + 4];
            float am[8] = {a0.x, a0.y, a0.z, a0.w, a1.x, a1.y, a1.z, a1.w};
            float bm[8] = {b0.x, b0.y, b0.z, b0.w, b1.x, b1.y, b1.z, b1.w};
#pragma unroll
            for (int i = 0; i < 8; ++i)
#pragma unroll
                for (int j = 0; j < 8; ++j) acc[i][j] += am[i] * bm[j];
        }
        __syncthreads();
    }
#pragma unroll
    for (int i = 0; i < 8; ++i) {
        int gr = r0 + ty * 8 + i;
        if (gr >= NU) continue;
        *(float4*)(C + (size_t)gr * HH + n0 + tx * 8) =
            make_float4(acc[i][0], acc[i][1], acc[i][2], acc[i][3]);
        *(float4*)(C + (size_t)gr * HH + n0 + tx * 8 + 4) =
            make_float4(acc[i][4], acc[i][5], acc[i][6], acc[i][7]);
    }
}

// ---------------- batched CSR build (all 3 edge types) ----------------
__global__ void k_zero3() {
    int i = blockIdx.x * 256 + threadIdx.x;
    if (i < 3 * NU) ((int*)g_cnt3)[i] = 0;
}
__global__ void k_hist3(const int* __restrict__ d0, const int* __restrict__ d1,
                        const int* __restrict__ d2, int E) {
    int t = blockIdx.y;
    const int* dst = t == 0 ? d0 : (t == 1 ? d1 : d2);
    int e = blockIdx.x * 256 + threadIdx.x;
    if (e < E) atomicAdd(&g_cnt3[t][dst[e]], 1);
}
// one block per type, 1024 threads, 4 items/thread, warp-shuffle scan
__global__ void __launch_bounds__(1024) k_scan3() {
    int t = blockIdx.x;
    __shared__ int warpsum[32];
    int tid = threadIdx.x;
    int lane = tid & 31, wid = tid >> 5;
    int carry = 0;
    for (int base = 0; base < NU; base += 4096) {
        int idx0 = base + tid * 4;
        int v[4];
        int s = 0;
#pragma unroll
        for (int q = 0; q < 4; ++q) {
            v[q] = (idx0 + q < NU) ? g_cnt3[t][idx0 + q] : 0;
            s += v[q];
        }
        int x = s;
#pragma unroll
        for (int o = 1; o < 32; o <<= 1) {
            int y = __shfl_up_sync(0xffffffffu, x, o);
            if (lane >= o) x += y;
        }
        if (lane == 31) warpsum[wid] = x;
        __syncthreads();
        if (wid == 0) {
            int w = warpsum[lane];
#pragma unroll
            for (int o = 1; o < 32; o <<= 1) {
                int y = __shfl_up_sync(0xffffffffu, w, o);
                if (lane >= o) w += y;
            }
            warpsum[lane] = w;
        }
        __syncthreads();
        int wprev = wid ? warpsum[wid - 1] : 0;
        int total = warpsum[31];
        int excl = carry + wprev + (x - s);
#pragma unroll
        for (int q = 0; q < 4; ++q) {
            if (idx0 + q < NU) {
                g_rp3[t][idx0 + q] = excl;
                g_cur3[t][idx0 + q] = excl;
            }
            excl += v[q];
        }
        carry += total;
        __syncthreads();
    }
    if (tid == 0) g_rp3[t][NU] = carry;
}
__global__ void k_scatter3(const int* __restrict__ d0, const int* __restrict__ d1,
                           const int* __restrict__ d2, int E) {
    int t = blockIdx.y;
    const int* dst = t == 0 ? d0 : (t == 1 ? d1 : d2);
    int e = blockIdx.x * 256 + threadIdx.x;
    if (e < E) {
        int p = atomicAdd(&g_cur3[t][dst[e]], 1);
        g_perm3[t][p] = e;
    }
}

// ---------------- permuted logits: write in CSR slot order ----------------
__global__ void k_permlog(const int* __restrict__ s0, const int* __restrict__ d0,
                          const int* __restrict__ s1, const int* __restrict__ d1,
                          const int* __restrict__ s2, const int* __restrict__ d2,
                          int E) {
    int t = blockIdx.y;
    const int* src = t == 0 ? s0 : (t == 1 ? s1 : s2);
    const int* dst = t == 0 ? d0 : (t == 1 ? d1 : d2);
    int j = blockIdx.x * 256 + threadIdx.x;
    if (j >= E) return;
    int e = g_perm3[t][j];
    int s = src[e];
    int d = dst[e];
    float4 s4 = *(const float4*)&g_a[2 * t][s * 4];
    float4 d4 = *(const float4*)&g_a[2 * t + 1][d * 4];
    g_pe[t][j] = make_float4(lrelu(s4.x + d4.x), lrelu(s4.y + d4.y),
                             lrelu(s4.z + d4.z), lrelu(s4.w + d4.w));
    g_psrc[t][j] = s;
}

// ---------------- warp-per-dst softmax + weighted aggregation (all 3 types) ----------------
__global__ void __launch_bounds__(256) k_gat2() {
    int t = blockIdx.y;
    int d = (blockIdx.x * 256 + threadIdx.x) >> 5;
    int lane = threadIdx.x & 31;
    if (d >= NU) return;
    int beg = g_rp3[t][d], end = g_rp3[t][d + 1];
    const float* hs = g_hs[t];
    const float4* pe = g_pe[t];
    const int* psrc = g_psrc[t];

    // phase A: per-head max (contiguous stream)
    float m0 = -INFINITY, m1 = -INFINITY, m2 = -INFINITY, m3 = -INFINITY;
    for (int j = beg + lane; j < end; j += 32) {
        float4 ev = pe[j];
        m0 = fmaxf(m0, ev.x); m1 = fmaxf(m1, ev.y);
        m2 = fmaxf(m2, ev.z); m3 = fmaxf(m3, ev.w);
    }
#pragma unroll
    for (int o = 16; o; o >>= 1) {
        m0 = fmaxf(m0, __shfl_xor_sync(0xffffffffu, m0, o));
        m1 = fmaxf(m1, __shfl_xor_sync(0xffffffffu, m1, o));
        m2 = fmaxf(m2, __shfl_xor_sync(0xffffffffu, m2, o));
        m3 = fmaxf(m3, __shfl_xor_sync(0xffffffffu, m3, o));
    }
    // phase B: per-head exp-sum
    float sm0 = 0.f, sm1 = 0.f, sm2 = 0.f, sm3 = 0.f;
    for (int j = beg + lane; j < end; j += 32) {
        float4 ev = pe[j];
        sm0 += __expf(ev.x - m0); sm1 += __expf(ev.y - m1);
        sm2 += __expf(ev.z - m2); sm3 += __expf(ev.w - m3);
    }
#pragma unroll
    for (int o = 16; o; o >>= 1) {
        sm0 += __shfl_xor_sync(0xffffffffu, sm0, o);
        sm1 += __shfl_xor_sync(0xffffffffu, sm1, o);
        sm2 += __shfl_xor_sync(0xffffffffu, sm2, o);
        sm3 += __shfl_xor_sync(0xffffffffu, sm3, o);
    }
    float i0 = 1.f / (sm0 + 1e-16f), i1 = 1.f / (sm1 + 1e-16f);
    float i2 = 1.f / (sm2 + 1e-16f), i3 = 1.f / (sm3 + 1e-16f);

    // phase C: chunked — each lane computes alpha for one edge, shfl-broadcast
    int h = lane >> 3;
    float4 acc0 = make_float4(0.f, 0.f, 0.f, 0.f);
    float4 acc1 = make_float4(0.f, 0.f, 0.f, 0.f);
    int coff = lane * 8;
    for (int base = beg; base < end; base += 32) {
        int j = base + lane;
        float4 a4 = make_float4(0.f, 0.f, 0.f, 0.f);
        int sj = 0;
        if (j < end) {
            float4 ev = pe[j];
            a4.x = __expf(ev.x - m0) * i0;
            a4.y = __expf(ev.y - m1) * i1;
            a4.z = __expf(ev.z - m2) * i2;
            a4.w = __expf(ev.w - m3) * i3;
            sj = psrc[j];
        }
        int cnt = min(32, end - base);
        for (int k = 0; k < cnt; ++k) {
            int sr  = __shfl_sync(0xffffffffu, sj, k);
            float ax = __shfl_sync(0xffffffffu, a4.x, k);
            float ay = __shfl_sync(0xffffffffu, a4.y, k);
            float az = __shfl_sync(0xffffffffu, a4.z, k);
            float aw = __shfl_sync(0xffffffffu, a4.w, k);
            float al = h == 0 ? ax : h == 1 ? ay : h == 2 ? az : aw;
            const float4* p = (const float4*)&hs[(size_t)sr * HH + coff];
            float4 v0 = p[0], v1 = p[1];
            acc0.x += al * v0.x; acc0.y += al * v0.y;
            acc0.z += al * v0.z; acc0.w += al * v0.w;
            acc1.x += al * v1.x; acc1.y += al * v1.y;
            acc1.z += al * v1.z; acc1.w += al * v1.w;
        }
    }
    float* op = &g_outT[t][(size_t)d * HH + coff];
    *(float4*)op = acc0;
    *(float4*)(op + 4) = acc1;
}

// ---------------- post output: elu(conv + bias) ----------------
__global__ void k_elu_post(const float* __restrict__ bias, float* __restrict__ dout) {
    int i = blockIdx.x * 256 + threadIdx.x;
    if (i >= NP * HH) return;
    float v = g_outT[2][i] + bias[i & 255];
    dout[i] = elu(v);
}

// ---------------- user output: elu(convA+convB+b1+b2) @ W_out + b_out ----------------
__global__ void __launch_bounds__(256, 2) k_gout(const float* __restrict__ W,
                                                 const float* __restrict__ bo,
                                                 const float* __restrict__ b1,
                                                 const float* __restrict__ b2,
                                                 float* __restrict__ dout) {
    __shared__ float As[32][132];
    __shared__ float Bs[32][68];
    int tid = threadIdx.x;
    int r0 = blockIdx.x * 128;
    int tx = tid & 15, ty = tid >> 4;
    float acc[8][4] = {};

    for (int kk = 0; kk < HH; kk += 32) {
#pragma unroll
        for (int i = 0; i < 4; ++i) {
            int f4 = i * 256 + tid;
            int row = f4 >> 3, kc4 = f4 & 7;
            int gr = r0 + row;
            float4 v = make_float4(0.f, 0.f, 0.f, 0.f);
            if (gr < NU) {
                float4 va = *(const float4*)&g_outT[0][(size_t)gr * HH + kk + kc4 * 4];
                float4 vb = *(const float4*)&g_outT[1][(size_t)gr * HH + kk + kc4 * 4];
                float4 bb1 = *(const float4*)(b1 + kk + kc4 * 4);
                float4 bb2 = *(const float4*)(b2 + kk + kc4 * 4);
                v.x = elu(va.x + vb.x + bb1.x + bb2.x);
                v.y = elu(va.y + vb.y + bb1.y + bb2.y);
                v.z = elu(va.z + vb.z + bb1.z + bb2.z);
                v.w = elu(va.w + vb.w + bb1.w + bb2.w);
            }
            As[kc4 * 4 + 0][row] = v.x; As[kc4 * 4 + 1][row] = v.y;
            As[kc4 * 4 + 2][row] = v.z; As[kc4 * 4 + 3][row] = v.w;
        }
#pragma unroll
        for (int i = 0; i < 2; ++i) {
            int f4 = i * 256 + tid;
            int k = f4 >> 4, c4 = f4 & 15;
            *(float4*)&Bs[k][c4 * 4] = *(const float4*)(W + (kk + k) * OUTD + c4 * 4);
        }
        __syncthreads();
#pragma unroll
        for (int k = 0; k < 32; ++k) {
            float4 a0 = *(float4*)&As[k][ty * 8];
            float4 a1 = *(float4*)&As[k][ty * 8 + 4];
            float4 bv = *(float4*)&Bs[k][tx * 4];
            float am[8] = {a0.x, a0.y, a0.z, a0.w, a1.x, a1.y, a1.z, a1.w};
            float bm[4] = {bv.x, bv.y, bv.z, bv.w};
#pragma unroll
            for (int i = 0; i < 8; ++i)
#pragma unroll
                for (int j = 0; j < 4; ++j) acc[i][j] += am[i] * bm[j];
        }
        __syncthreads();
    }
    float4 bb = *(const float4*)(bo + tx * 4);
#pragma unroll
    for (int i = 0; i < 8; ++i) {
        int gr = r0 + ty * 8 + i;
        if (gr >= NU) continue;
        *(float4*)(dout + (size_t)gr * OUTD + tx * 4) =
            make_float4(acc[i][0] + bb.x, acc[i][1] + bb.y,
                        acc[i][2] + bb.z, acc[i][3] + bb.w);
    }
}

// ---------------- launch ----------------
extern "C" void kernel_launch(void* const* d_in, const int* in_sizes, int n_in,
                              void* d_out, int out_size) {
    const float* x_user     = (const float*)d_in[0];
    const float* x_post     = (const float*)d_in[1];
    const int*   src_u2u    = (const int*)d_in[2];
    const int*   dst_u2u    = (const int*)d_in[3];
    const int*   src_p2u    = (const int*)d_in[4];
    const int*   dst_p2u    = (const int*)d_in[5];
    const int*   src_u2p    = (const int*)d_in[6];
    const int*   dst_u2p    = (const int*)d_in[7];
    const float* W_proj     = (const float*)d_in[8];
    const float* b_proj     = (const float*)d_in[9];
    const float* lin_u2u    = (const float*)d_in[10];
    const float* att_s_u2u  = (const float*)d_in[11];
    const float* att_d_u2u  = (const float*)d_in[12];
    const float* bias_u2u   = (const float*)d_in[13];
    const float* lin_p2u    = (const float*)d_in[14];
    const float* att_s_p2u  = (const float*)d_in[15];
    const float* att_d_p2u  = (const float*)d_in[16];
    const float* bias_p2u   = (const float*)d_in[17];
    const float* lin_u2p    = (const float*)d_in[18];
    const float* att_s_u2p  = (const float*)d_in[19];
    const float* att_d_u2p  = (const float*)d_in[20];
    const float* bias_u2p   = (const float*)d_in[21];
    const float* W_out      = (const float*)d_in[22];
    const float* b_out      = (const float*)d_in[23];
    float* out = (float*)d_out;
    int E = in_sizes[2];
    int gE = (E + 255) / 256;

    k_fold<<<6, 256>>>(lin_u2u, lin_p2u, lin_u2p,
                       att_s_u2u, att_d_u2u, att_s_p2u, att_d_p2u, att_s_u2p, att_d_u2p);
    // CSR build is independent of the GEMMs; put it first so its atomics/scan
    // overlap tail effects of nothing — but the single stream just runs in order.
    k_zero3<<<(3 * NU + 255) / 256, 256>>>();
    k_hist3<<<dim3(gE, 3), 256>>>(dst_u2u, dst_p2u, dst_u2p, E);
    k_scan3<<<3, 1024>>>();
    k_scatter3<<<dim3(gE, 3), 256>>>(dst_u2u, dst_p2u, dst_u2p, E);

    k_proj<<<(NU + NP + 127) / 128, 256>>>(x_user, x_post, W_proj, b_proj);
    k_att2<<<dim3((NU + 255) / 256, 2), 256>>>();
    k_lin<<<dim3((NU + 127) / 128, 2, 3), 256>>>(lin_u2u, lin_p2u, lin_u2p);

    k_permlog<<<dim3(gE, 3), 256>>>(src_u2u, dst_u2u, src_p2u, dst_p2u,
                                    src_u2p, dst_u2p, E);
    k_gat2<<<dim3((NU * 32 + 255) / 256, 3), 256>>>();

    k_elu_post<<<(NP * HH + 255) / 256, 256>>>(bias_u2p, out + (size_t)NU * OUTD);
    k_gout<<<(NU + 127) / 128, 256>>>(W_out, b_out, bias_u2u, bias_p2u, out);
}

// round 3
// speedup vs baseline: 1.3664x; 1.0576x over previous
#include <cuda_runtime.h>
#include <math.h>

#define NU 50000
#define NP 50000
#define NEMAX 400000
#define IND 128
#define HID 64
#define NH 4
#define HH 256   // HEADS*HID
#define OUTD 64
#define SCHUNK 4096
#define NCHUNK ((NU + SCHUNK - 1) / SCHUNK)   // 13

// f32x2 packed math (Blackwell sm_10x)
#define FMA_F32X2(d, a, b, c) \
    asm("fma.rn.f32x2 %0, %1, %2, %3;" : "=l"(d) : "l"(a), "l"(b), "l"(c))

// ---------------- scratch (static device globals; no allocation) ----------------
__device__ float  g_hu[NU * HID];
__device__ float  g_hp[NP * HID];
__device__ float  g_z[3][NU * HH];       // aggregated (per-head) features: [d][h*64+k]
__device__ float  g_a[6][NU * NH];       // folded attention scalars
__device__ float  g_wf[6][HID * NH];     // folded lin@att^T
__device__ float4 g_pe[3][NEMAX];        // permuted edge logits (CSR slot order)
__device__ int    g_psrc[3][NEMAX];      // permuted src (CSR slot order)
__device__ int    g_cnt3[3][NU];
__device__ int    g_rp3[3][NU + 1];
__device__ int    g_cur3[3][NU];
__device__ int    g_perm3[3][NEMAX];
__device__ int    g_csum[3][NCHUNK];
__device__ int    g_coff[3][NCHUNK];
__device__ float  g_outT[3][NU * HH];    // per-type conv outputs (0:u2u, 1:p2u, 2:u2p)

__device__ __forceinline__ float lrelu(float x) {
    return fmaxf(x, 0.f) + 0.2f * fminf(x, 0.f);
}
__device__ __forceinline__ float elu(float x) {
    return x > 0.f ? x : expm1f(x);
}

// ---------------- fold lin @ att^T into [64,4] per (edge-type, src/dst) ----------------
__global__ void k_fold(const float* __restrict__ l0, const float* __restrict__ l1,
                       const float* __restrict__ l2,
                       const float* __restrict__ a0, const float* __restrict__ a1,
                       const float* __restrict__ a2, const float* __restrict__ a3,
                       const float* __restrict__ a4, const float* __restrict__ a5) {
    int combo = blockIdx.x;  // 0..5
    const float* lin = combo < 2 ? l0 : (combo < 4 ? l1 : l2);
    const float* att = combo == 0 ? a0 : combo == 1 ? a1 : combo == 2 ? a2
                     : combo == 3 ? a3 : combo == 4 ? a4 : a5;
    int t = threadIdx.x;          // 256 threads = 64 cin x 4 heads
    int cin = t >> 2, h = t & 3;
    const float* lr = lin + cin * HH + h * HID;
    const float* ar = att + h * HID;
    float s = 0.f;
#pragma unroll 8
    for (int c = 0; c < HID; ++c) s += lr[c] * ar[c];
    g_wf[combo][cin * NH + h] = s;
}

// ---------------- projection: [100000,128] @ [128,64] + b  ->  g_hu / g_hp ----------------
__global__ void __launch_bounds__(256, 2) k_proj(const float* __restrict__ xu,
                                                 const float* __restrict__ xp,
                                                 const float* __restrict__ W,
                                                 const float* __restrict__ b) {
    __shared__ float As[32][132];   // [k][m], padded
    __shared__ float Bs[32][68];    // [k][n], padded
    int tid = threadIdx.x;
    int r0 = blockIdx.x * 128;
    int tx = tid & 15, ty = tid >> 4;
    float acc[8][4] = {};

    for (int kk = 0; kk < IND; kk += 32) {
#pragma unroll
        for (int i = 0; i < 4; ++i) {
            int f4 = i * 256 + tid;
            int row = f4 >> 3;
            int kc4 = f4 & 7;
            int gr = r0 + row;
            float4 v = make_float4(0.f, 0.f, 0.f, 0.f);
            if (gr < NU + NP) {
                const float* srcp = gr < NU ? xu + (size_t)gr * IND
                                            : xp + (size_t)(gr - NU) * IND;
                v = *(const float4*)(srcp + kk + kc4 * 4);
            }
            As[kc4 * 4 + 0][row] = v.x; As[kc4 * 4 + 1][row] = v.y;
            As[kc4 * 4 + 2][row] = v.z; As[kc4 * 4 + 3][row] = v.w;
        }
#pragma unroll
        for (int i = 0; i < 2; ++i) {
            int f4 = i * 256 + tid;
            int k = f4 >> 4, c4 = f4 & 15;
            *(float4*)&Bs[k][c4 * 4] = *(const float4*)(W + (kk + k) * 64 + c4 * 4);
        }
        __syncthreads();
#pragma unroll
        for (int k = 0; k < 32; ++k) {
            float4 a0 = *(float4*)&As[k][ty * 8];
            float4 a1 = *(float4*)&As[k][ty * 8 + 4];
            float4 bv = *(float4*)&Bs[k][tx * 4];
            float am[8] = {a0.x, a0.y, a0.z, a0.w, a1.x, a1.y, a1.z, a1.w};
            float bm[4] = {bv.x, bv.y, bv.z, bv.w};
#pragma unroll
            for (int i = 0; i < 8; ++i)
#pragma unroll
                for (int j = 0; j < 4; ++j) acc[i][j] += am[i] * bm[j];
        }
        __syncthreads();
    }
    float4 bb = *(const float4*)(b + tx * 4);
#pragma unroll
    for (int i = 0; i < 8; ++i) {
        int gr = r0 + ty * 8 + i;
        if (gr >= NU + NP) continue;
        float4 o = make_float4(acc[i][0] + bb.x, acc[i][1] + bb.y,
                               acc[i][2] + bb.z, acc[i][3] + bb.w);
        float* dst = gr < NU ? g_hu + (size_t)gr * HID
                             : g_hp + (size_t)(gr - NU) * HID;
        *(float4*)(dst + tx * 4) = o;
    }
}

// ---------------- attention scalars, H read once per node ----------------
__global__ void k_att2() {
    int part = blockIdx.y;
    __shared__ float wf[4][HID * NH];
    int nz = part ? 2 : 4;
    int zsU[4] = {0, 1, 3, 4};
    int zsP[2] = {2, 5};
#pragma unroll
    for (int zi = 0; zi < 4; ++zi) {
        if (zi < nz) {
            int z = part ? zsP[zi] : zsU[zi];
            wf[zi][threadIdx.x] = g_wf[z][threadIdx.x];
        }
    }
    __syncthreads();
    int node = blockIdx.x * 256 + threadIdx.x;
    if (node >= NU) return;
    const float* hr = (part ? g_hp : g_hu) + (size_t)node * HID;
    float acc[4][4] = {};
#pragma unroll
    for (int c = 0; c < HID; c += 4) {
        float4 h4 = *(const float4*)(hr + c);
#pragma unroll
        for (int zi = 0; zi < 4; ++zi) {
            if (zi >= nz) break;
#pragma unroll
            for (int hh = 0; hh < 4; ++hh) {
                acc[zi][hh] += h4.x * wf[zi][(c + 0) * 4 + hh]
                             + h4.y * wf[zi][(c + 1) * 4 + hh]
                             + h4.z * wf[zi][(c + 2) * 4 + hh]
                             + h4.w * wf[zi][(c + 3) * 4 + hh];
            }
        }
    }
#pragma unroll
    for (int zi = 0; zi < 4; ++zi) {
        if (zi >= nz) break;
        int z = part ? zsP[zi] : zsU[zi];
        *(float4*)&g_a[z][node * 4] =
            make_float4(acc[zi][0], acc[zi][1], acc[zi][2], acc[zi][3]);
    }
}

// ---------------- batched CSR build ----------------
__global__ void k_zero3() {
    int i = blockIdx.x * 256 + threadIdx.x;
    if (i < 3 * NU) ((int*)g_cnt3)[i] = 0;
}
__global__ void k_hist3(const int* __restrict__ d0, const int* __restrict__ d1,
                        const int* __restrict__ d2, int E) {
    int t = blockIdx.y;
    const int* dst = t == 0 ? d0 : (t == 1 ? d1 : d2);
    int e = blockIdx.x * 256 + threadIdx.x;
    if (e < E) atomicAdd(&g_cnt3[t][dst[e]], 1);
}
// phase a: per-chunk local scan (grid = NCHUNK x 3)
__global__ void __launch_bounds__(1024) k_scan_a() {
    int t = blockIdx.y, chunk = blockIdx.x;
    __shared__ int warpsum[32];
    int tid = threadIdx.x;
    int lane = tid & 31, wid = tid >> 5;
    int idx0 = chunk * SCHUNK + tid * 4;
    int v[4];
    int s = 0;
#pragma unroll
    for (int q = 0; q < 4; ++q) {
        v[q] = (idx0 + q < NU) ? g_cnt3[t][idx0 + q] : 0;
        s += v[q];
    }
    int x = s;
#pragma unroll
    for (int o = 1; o < 32; o <<= 1) {
        int y = __shfl_up_sync(0xffffffffu, x, o);
        if (lane >= o) x += y;
    }
    if (lane == 31) warpsum[wid] = x;
    __syncthreads();
    if (wid == 0) {
        int w = warpsum[lane];
#pragma unroll
        for (int o = 1; o < 32; o <<= 1) {
            int y = __shfl_up_sync(0xffffffffu, w, o);
            if (lane >= o) w += y;
        }
        warpsum[lane] = w;
    }
    __syncthreads();
    int wprev = wid ? warpsum[wid - 1] : 0;
    int excl = wprev + (x - s);
#pragma unroll
    for (int q = 0; q < 4; ++q) {
        if (idx0 + q < NU) g_rp3[t][idx0 + q] = excl;
        excl += v[q];
    }
    if (tid == 0) g_csum[t][chunk] = warpsum[31];
}
// phase b: scan the 13 chunk totals per type (1 block, 3 warps)
__global__ void k_scan_b() {
    int w = threadIdx.x >> 5;   // type
    int lane = threadIdx.x & 31;
    if (w >= 3) return;
    int val = lane < NCHUNK ? g_csum[w][lane] : 0;
    int x = val;
#pragma unroll
    for (int o = 1; o < 32; o <<= 1) {
        int y = __shfl_up_sync(0xffffffffu, x, o);
        if (lane >= o) x += y;
    }
    if (lane < NCHUNK) g_coff[w][lane] = x - val;
    if (lane == 31) g_rp3[w][NU] = x;
}
// phase c: add chunk offsets, fill g_cur
__global__ void __launch_bounds__(1024) k_scan_c() {
    int t = blockIdx.y, chunk = blockIdx.x;
    int off = g_coff[t][chunk];
    int idx0 = chunk * SCHUNK + threadIdx.x * 4;
#pragma unroll
    for (int q = 0; q < 4; ++q) {
        int i = idx0 + q;
        if (i < NU) {
            int r = g_rp3[t][i] + off;
            g_rp3[t][i] = r;
            g_cur3[t][i] = r;
        }
    }
}
__global__ void k_scatter3(const int* __restrict__ d0, const int* __restrict__ d1,
                           const int* __restrict__ d2, int E) {
    int t = blockIdx.y;
    const int* dst = t == 0 ? d0 : (t == 1 ? d1 : d2);
    int e = blockIdx.x * 256 + threadIdx.x;
    if (e < E) {
        int p = atomicAdd(&g_cur3[t][dst[e]], 1);
        g_perm3[t][p] = e;
    }
}

// ---------------- permuted logits: write in CSR slot order ----------------
__global__ void k_permlog(const int* __restrict__ s0, const int* __restrict__ d0,
                          const int* __restrict__ s1, const int* __restrict__ d1,
                          const int* __restrict__ s2, const int* __restrict__ d2,
                          int E) {
    int t = blockIdx.y;
    const int* src = t == 0 ? s0 : (t == 1 ? s1 : s2);
    const int* dst = t == 0 ? d0 : (t == 1 ? d1 : d2);
    int j = blockIdx.x * 256 + threadIdx.x;
    if (j >= E) return;
    int e = g_perm3[t][j];
    int s = src[e];
    int d = dst[e];
    float4 s4 = *(const float4*)&g_a[2 * t][s * 4];
    float4 d4 = *(const float4*)&g_a[2 * t + 1][d * 4];
    g_pe[t][j] = make_float4(lrelu(s4.x + d4.x), lrelu(s4.y + d4.y),
                             lrelu(s4.z + d4.z), lrelu(s4.w + d4.w));
    g_psrc[t][j] = s;
}

// ---------------- warp-per-dst softmax + aggregation in HID space ----------------
// z[d,h,:] = sum_e alpha_e,h * h_src[src_e, :]   (gather 256B/edge instead of 1KB)
__global__ void __launch_bounds__(256) k_gat3() {
    int t = blockIdx.y;
    int d = (blockIdx.x * 256 + threadIdx.x) >> 5;
    int lane = threadIdx.x & 31;
    if (d >= NU) return;
    int beg = g_rp3[t][d], end = g_rp3[t][d + 1];
    const float* hsrc = (t == 1) ? g_hp : g_hu;
    const float4* pe = g_pe[t];
    const int* psrc = g_psrc[t];

    // phase A: per-head max
    float m0 = -INFINITY, m1 = -INFINITY, m2 = -INFINITY, m3 = -INFINITY;
    for (int j = beg + lane; j < end; j += 32) {
        float4 ev = pe[j];
        m0 = fmaxf(m0, ev.x); m1 = fmaxf(m1, ev.y);
        m2 = fmaxf(m2, ev.z); m3 = fmaxf(m3, ev.w);
    }
#pragma unroll
    for (int o = 16; o; o >>= 1) {
        m0 = fmaxf(m0, __shfl_xor_sync(0xffffffffu, m0, o));
        m1 = fmaxf(m1, __shfl_xor_sync(0xffffffffu, m1, o));
        m2 = fmaxf(m2, __shfl_xor_sync(0xffffffffu, m2, o));
        m3 = fmaxf(m3, __shfl_xor_sync(0xffffffffu, m3, o));
    }
    // phase B: per-head exp-sum
    float sm0 = 0.f, sm1 = 0.f, sm2 = 0.f, sm3 = 0.f;
    for (int j = beg + lane; j < end; j += 32) {
        float4 ev = pe[j];
        sm0 += __expf(ev.x - m0); sm1 += __expf(ev.y - m1);
        sm2 += __expf(ev.z - m2); sm3 += __expf(ev.w - m3);
    }
#pragma unroll
    for (int o = 16; o; o >>= 1) {
        sm0 += __shfl_xor_sync(0xffffffffu, sm0, o);
        sm1 += __shfl_xor_sync(0xffffffffu, sm1, o);
        sm2 += __shfl_xor_sync(0xffffffffu, sm2, o);
        sm3 += __shfl_xor_sync(0xffffffffu, sm3, o);
    }
    float i0 = 1.f / (sm0 + 1e-16f), i1 = 1.f / (sm1 + 1e-16f);
    float i2 = 1.f / (sm2 + 1e-16f), i3 = 1.f / (sm3 + 1e-16f);

    // phase C: lane covers channels [lane*2, lane*2+2) for all 4 heads
    float acc[4][2] = {};
    int c0 = lane * 2;
    for (int base = beg; base < end; base += 32) {
        int j = base + lane;
        float4 a4 = make_float4(0.f, 0.f, 0.f, 0.f);
        int sj = 0;
        if (j < end) {
            float4 ev = pe[j];
            a4.x = __expf(ev.x - m0) * i0;
            a4.y = __expf(ev.y - m1) * i1;
            a4.z = __expf(ev.z - m2) * i2;
            a4.w = __expf(ev.w - m3) * i3;
            sj = psrc[j];
        }
        int cnt = min(32, end - base);
        for (int k = 0; k < cnt; ++k) {
            int sr  = __shfl_sync(0xffffffffu, sj, k);
            float ax = __shfl_sync(0xffffffffu, a4.x, k);
            float ay = __shfl_sync(0xffffffffu, a4.y, k);
            float az = __shfl_sync(0xffffffffu, a4.z, k);
            float aw = __shfl_sync(0xffffffffu, a4.w, k);
            float2 v = *(const float2*)&hsrc[(size_t)sr * HID + c0];
            acc[0][0] += ax * v.x; acc[0][1] += ax * v.y;
            acc[1][0] += ay * v.x; acc[1][1] += ay * v.y;
            acc[2][0] += az * v.x; acc[2][1] += az * v.y;
            acc[3][0] += aw * v.x; acc[3][1] += aw * v.y;
        }
    }
    float* zp = &g_z[t][(size_t)d * HH];
#pragma unroll
    for (int h = 0; h < 4; ++h)
        *(float2*)&zp[h * HID + c0] = make_float2(acc[h][0], acc[h][1]);
}

// ---------------- per-head GEMM: outT[t][d, h*64+c] = z[t][d,h,:] @ lin_t[:, h*64+c]
// f32x2 packed FMAs with duplicated-A smem. Grid: (391, 4 heads, 3 types).
__global__ void __launch_bounds__(256, 2) k_hg(const float* __restrict__ l0,
                                               const float* __restrict__ l1,
                                               const float* __restrict__ l2) {
    __shared__ float Ad[32][260];   // duplicated A: [k][2*m], row stride 260 (16B aligned)
    __shared__ float Bs[32][68];    // [k][n]
    int t = blockIdx.z, h = blockIdx.y;
    const float* lin = (t == 0 ? l0 : (t == 1 ? l1 : l2));
    const float* A = g_z[t];        // row d: A + d*256 + h*64
    float* C = g_outT[t];
    int tid = threadIdx.x;
    int r0 = blockIdx.x * 128;
    int tx = tid & 15, ty = tid >> 4;

    unsigned long long acc[8][2];   // packed col-pairs: [i][0]=(c0,c1), [i][1]=(c2,c3)
#pragma unroll
    for (int i = 0; i < 8; ++i) { acc[i][0] = 0ull; acc[i][1] = 0ull; }

    for (int kk = 0; kk < HID; kk += 32) {
        // A tile: 128 rows x 32 k = 1024 f4, 4/thread; write each value twice
#pragma unroll
        for (int i = 0; i < 4; ++i) {
            int f4 = i * 256 + tid;
            int row = f4 >> 3, kc4 = f4 & 7;
            int gr = r0 + row;
            float4 v = make_float4(0.f, 0.f, 0.f, 0.f);
            if (gr < NU)
                v = *(const float4*)(A + (size_t)gr * HH + h * HID + kk + kc4 * 4);
            Ad[kc4 * 4 + 0][2 * row] = v.x; Ad[kc4 * 4 + 0][2 * row + 1] = v.x;
            Ad[kc4 * 4 + 1][2 * row] = v.y; Ad[kc4 * 4 + 1][2 * row + 1] = v.y;
            Ad[kc4 * 4 + 2][2 * row] = v.z; Ad[kc4 * 4 + 2][2 * row + 1] = v.z;
            Ad[kc4 * 4 + 3][2 * row] = v.w; Ad[kc4 * 4 + 3][2 * row + 1] = v.w;
        }
        // B tile: 32 k x 64 n = 512 f4, 2/thread
#pragma unroll
        for (int i = 0; i < 2; ++i) {
            int f4 = i * 256 + tid;
            int k = f4 >> 4, c4 = f4 & 15;
            *(float4*)&Bs[k][c4 * 4] =
                *(const float4*)(lin + (size_t)(kk + k) * HH + h * HID + c4 * 4);
        }
        __syncthreads();
#pragma unroll
        for (int k = 0; k < 32; ++k) {
            // duplicated a pairs: (a_i, a_i)
            const ulonglong2* ap = (const ulonglong2*)&Ad[k][ty * 16];
            ulonglong2 a01 = ap[0], a23 = ap[1], a45 = ap[2], a67 = ap[3];
            ulonglong2 bv = *(const ulonglong2*)&Bs[k][tx * 4];   // (b0,b1),(b2,b3)
            FMA_F32X2(acc[0][0], a01.x, bv.x, acc[0][0]);
            FMA_F32X2(acc[0][1], a01.x, bv.y, acc[0][1]);
            FMA_F32X2(acc[1][0], a01.y, bv.x, acc[1][0]);
            FMA_F32X2(acc[1][1], a01.y, bv.y, acc[1][1]);
            FMA_F32X2(acc[2][0], a23.x, bv.x, acc[2][0]);
            FMA_F32X2(acc[2][1], a23.x, bv.y, acc[2][1]);
            FMA_F32X2(acc[3][0], a23.y, bv.x, acc[3][0]);
            FMA_F32X2(acc[3][1], a23.y, bv.y, acc[3][1]);
            FMA_F32X2(acc[4][0], a45.x, bv.x, acc[4][0]);
            FMA_F32X2(acc[4][1], a45.x, bv.y, acc[4][1]);
            FMA_F32X2(acc[5][0], a45.y, bv.x, acc[5][0]);
            FMA_F32X2(acc[5][1], a45.y, bv.y, acc[5][1]);
            FMA_F32X2(acc[6][0], a67.x, bv.x, acc[6][0]);
            FMA_F32X2(acc[6][1], a67.x, bv.y, acc[6][1]);
            FMA_F32X2(acc[7][0], a67.y, bv.x, acc[7][0]);
            FMA_F32X2(acc[7][1], a67.y, bv.y, acc[7][1]);
        }
        __syncthreads();
    }
#pragma unroll
    for (int i = 0; i < 8; ++i) {
        int gr = r0 + ty * 8 + i;
        if (gr >= NU) continue;
        float2 p0 = *(float2*)&acc[i][0];
        float2 p1 = *(float2*)&acc[i][1];
        *(float4*)(C + (size_t)gr * HH + h * HID + tx * 4) =
            make_float4(p0.x, p0.y, p1.x, p1.y);
    }
}

// ---------------- post output: elu(conv + bias) ----------------
__global__ void k_elu_post(const float* __restrict__ bias, float* __restrict__ dout) {
    int i = blockIdx.x * 256 + threadIdx.x;
    if (i >= NP * HH) return;
    float v = g_outT[2][i] + bias[i & 255];
    dout[i] = elu(v);
}

// ---------------- user output: elu(convA+convB+b1+b2) @ W_out + b_out ----------------
__global__ void __launch_bounds__(256, 2) k_gout(const float* __restrict__ W,
                                                 const float* __restrict__ bo,
                                                 const float* __restrict__ b1,
                                                 const float* __restrict__ b2,
                                                 float* __restrict__ dout) {
    __shared__ float As[32][132];
    __shared__ float Bs[32][68];
    int tid = threadIdx.x;
    int r0 = blockIdx.x * 128;
    int tx = tid & 15, ty = tid >> 4;
    float acc[8][4] = {};

    for (int kk = 0; kk < HH; kk += 32) {
#pragma unroll
        for (int i = 0; i < 4; ++i) {
            int f4 = i * 256 + tid;
            int row = f4 >> 3, kc4 = f4 & 7;
            int gr = r0 + row;
            float4 v = make_float4(0.f, 0.f, 0.f, 0.f);
            if (gr < NU) {
                float4 va = *(const float4*)&g_outT[0][(size_t)gr * HH + kk + kc4 * 4];
                float4 vb = *(const float4*)&g_outT[1][(size_t)gr * HH + kk + kc4 * 4];
                float4 bb1 = *(const float4*)(b1 + kk + kc4 * 4);
                float4 bb2 = *(const float4*)(b2 + kk + kc4 * 4);
                v.x = elu(va.x + vb.x + bb1.x + bb2.x);
                v.y = elu(va.y + vb.y + bb1.y + bb2.y);
                v.z = elu(va.z + vb.z + bb1.z + bb2.z);
                v.w = elu(va.w + vb.w + bb1.w + bb2.w);
            }
            As[kc4 * 4 + 0][row] = v.x; As[kc4 * 4 + 1][row] = v.y;
            As[kc4 * 4 + 2][row] = v.z; As[kc4 * 4 + 3][row] = v.w;
        }
#pragma unroll
        for (int i = 0; i < 2; ++i) {
            int f4 = i * 256 + tid;
            int k = f4 >> 4, c4 = f4 & 15;
            *(float4*)&Bs[k][c4 * 4] = *(const float4*)(W + (kk + k) * OUTD + c4 * 4);
        }
        __syncthreads();
#pragma unroll
        for (int k = 0; k < 32; ++k) {
            float4 a0 = *(float4*)&As[k][ty * 8];
            float4 a1 = *(float4*)&As[k][ty * 8 + 4];
            float4 bv = *(float4*)&Bs[k][tx * 4];
            float am[8] = {a0.x, a0.y, a0.z, a0.w, a1.x, a1.y, a1.z, a1.w};
            float bm[4] = {bv.x, bv.y, bv.z, bv.w};
#pragma unroll
            for (int i = 0; i < 8; ++i)
#pragma unroll
                for (int j = 0; j < 4; ++j) acc[i][j] += am[i] * bm[j];
        }
        __syncthreads();
    }
    float4 bb = *(const float4*)(bo + tx * 4);
#pragma unroll
    for (int i = 0; i < 8; ++i) {
        int gr = r0 + ty * 8 + i;
        if (gr >= NU) continue;
        *(float4*)(dout + (size_t)gr * OUTD + tx * 4) =
            make_float4(acc[i][0] + bb.x, acc[i][1] + bb.y,
                        acc[i][2] + bb.z, acc[i][3] + bb.w);
    }
}

// ---------------- launch ----------------
extern "C" void kernel_launch(void* const* d_in, const int* in_sizes, int n_in,
                              void* d_out, int out_size) {
    const float* x_user     = (const float*)d_in[0];
    const float* x_post     = (const float*)d_in[1];
    const int*   src_u2u    = (const int*)d_in[2];
    const int*   dst_u2u    = (const int*)d_in[3];
    const int*   src_p2u    = (const int*)d_in[4];
    const int*   dst_p2u    = (const int*)d_in[5];
    const int*   src_u2p    = (const int*)d_in[6];
    const int*   dst_u2p    = (const int*)d_in[7];
    const float* W_proj     = (const float*)d_in[8];
    const float* b_proj     = (const float*)d_in[9];
    const float* lin_u2u    = (const float*)d_in[10];
    const float* att_s_u2u  = (const float*)d_in[11];
    const float* att_d_u2u  = (const float*)d_in[12];
    const float* bias_u2u   = (const float*)d_in[13];
    const float* lin_p2u    = (const float*)d_in[14];
    const float* att_s_p2u  = (const float*)d_in[15];
    const float* att_d_p2u  = (const float*)d_in[16];
    const float* bias_p2u   = (const float*)d_in[17];
    const float* lin_u2p    = (const float*)d_in[18];
    const float* att_s_u2p  = (const float*)d_in[19];
    const float* att_d_u2p  = (const float*)d_in[20];
    const float* bias_u2p   = (const float*)d_in[21];
    const float* W_out      = (const float*)d_in[22];
    const float* b_out      = (const float*)d_in[23];
    float* out = (float*)d_out;
    int E = in_sizes[2];
    int gE = (E + 255) / 256;

    k_fold<<<6, 256>>>(lin_u2u, lin_p2u, lin_u2p,
                       att_s_u2u, att_d_u2u, att_s_p2u, att_d_p2u, att_s_u2p, att_d_u2p);
    k_zero3<<<(3 * NU + 255) / 256, 256>>>();
    k_hist3<<<dim3(gE, 3), 256>>>(dst_u2u, dst_p2u, dst_u2p, E);
    k_scan_a<<<dim3(NCHUNK, 3), 1024>>>();
    k_scan_b<<<1, 96>>>();
    k_scan_c<<<dim3(NCHUNK, 3), 1024>>>();
    k_scatter3<<<dim3(gE, 3), 256>>>(dst_u2u, dst_p2u, dst_u2p, E);

    k_proj<<<(NU + NP + 127) / 128, 256>>>(x_user, x_post, W_proj, b_proj);
    k_att2<<<dim3((NU + 255) / 256, 2), 256>>>();

    k_permlog<<<dim3(gE, 3), 256>>>(src_u2u, dst_u2u, src_p2u, dst_p2u,
                                    src_u2p, dst_u2p, E);
    k_gat3<<<dim3((NU * 32 + 255) / 256, 3), 256>>>();
    k_hg<<<dim3((NU + 127) / 128, NH, 3), 256>>>(lin_u2u, lin_p2u, lin_u2p);

    k_elu_post<<<(NP * HH + 255) / 256, 256>>>(bias_u2p, out + (size_t)NU * OUTD);
    k_gout<<<(NU + 127) / 128, 256>>>(W_out, b_out, bias_u2u, bias_p2u, out);
}

// round 4
// speedup vs baseline: 1.5258x; 1.1167x over previous
#include <cuda_runtime.h>
#include <math.h>

#define NU 50000
#define NP 50000
#define NEMAX 400000
#define IND 128
#define HID 64
#define NH 4
#define HH 256   // HEADS*HID
#define OUTD 64
#define SCHUNK 4096
#define NCHUNK ((NU + SCHUNK - 1) / SCHUNK)   // 13

// f32x2 packed math (Blackwell sm_10x)
#define FMA_F32X2(d, a, b, c) \
    asm("fma.rn.f32x2 %0, %1, %2, %3;" : "=l"(d) : "l"(a), "l"(b), "l"(c))

// ---------------- scratch (static device globals; no allocation) ----------------
__device__ float  g_hu[NU * HID];
__device__ float  g_hp[NP * HID];
__device__ float  g_z[3][NU * HH];       // aggregated per-head features
__device__ float  g_a[6][NU * NH];       // folded attention scalars
__device__ float  g_wf[6][HID * NH];     // folded lin@att^T
__device__ float4 g_pe[3][NEMAX];        // edge logits in CSR slot order
__device__ int    g_psrc[3][NEMAX];      // src in CSR slot order
__device__ int    g_cnt3[3][NU];
__device__ int    g_rp3[3][NU + 1];
__device__ int    g_cur3[3][NU];
__device__ int    g_csum[3][NCHUNK];
__device__ int    g_coff[3][NCHUNK];
__device__ float  g_outU[NU * HH];       // elu(conv_u2u + conv_p2u + biases)

__device__ __forceinline__ float lrelu(float x) {
    return fmaxf(x, 0.f) + 0.2f * fminf(x, 0.f);
}
__device__ __forceinline__ float elu(float x) {
    return x > 0.f ? x : expm1f(x);
}

// ---------------- fold lin @ att^T into [64,4] per (edge-type, src/dst) ----------------
__global__ void k_fold(const float* __restrict__ l0, const float* __restrict__ l1,
                       const float* __restrict__ l2,
                       const float* __restrict__ a0, const float* __restrict__ a1,
                       const float* __restrict__ a2, const float* __restrict__ a3,
                       const float* __restrict__ a4, const float* __restrict__ a5) {
    int combo = blockIdx.x;  // 0..5
    const float* lin = combo < 2 ? l0 : (combo < 4 ? l1 : l2);
    const float* att = combo == 0 ? a0 : combo == 1 ? a1 : combo == 2 ? a2
                     : combo == 3 ? a3 : combo == 4 ? a4 : a5;
    int t = threadIdx.x;          // 256 threads = 64 cin x 4 heads
    int cin = t >> 2, h = t & 3;
    const float* lr = lin + cin * HH + h * HID;
    const float* ar = att + h * HID;
    float s = 0.f;
#pragma unroll 8
    for (int c = 0; c < HID; ++c) s += lr[c] * ar[c];
    g_wf[combo][cin * NH + h] = s;
}

// ---------------- projection (f32x2): [100000,128]@[128,64] + b -> g_hu / g_hp ----------------
__global__ void __launch_bounds__(256, 2) k_proj(const float* __restrict__ xu,
                                                 const float* __restrict__ xp,
                                                 const float* __restrict__ W,
                                                 const float* __restrict__ b) {
    __shared__ float Ad[32][260];   // duplicated A: [k][2*m]
    __shared__ float Bs[32][68];
    int tid = threadIdx.x;
    int r0 = blockIdx.x * 128;
    int tx = tid & 15, ty = tid >> 4;
    unsigned long long acc[8][2];
#pragma unroll
    for (int i = 0; i < 8; ++i) { acc[i][0] = 0ull; acc[i][1] = 0ull; }

    for (int kk = 0; kk < IND; kk += 32) {
#pragma unroll
        for (int i = 0; i < 4; ++i) {
            int f4 = i * 256 + tid;
            int row = f4 >> 3, kc4 = f4 & 7;
            int gr = r0 + row;
            float4 v = make_float4(0.f, 0.f, 0.f, 0.f);
            if (gr < NU + NP) {
                const float* srcp = gr < NU ? xu + (size_t)gr * IND
                                            : xp + (size_t)(gr - NU) * IND;
                v = *(const float4*)(srcp + kk + kc4 * 4);
            }
            Ad[kc4 * 4 + 0][2 * row] = v.x; Ad[kc4 * 4 + 0][2 * row + 1] = v.x;
            Ad[kc4 * 4 + 1][2 * row] = v.y; Ad[kc4 * 4 + 1][2 * row + 1] = v.y;
            Ad[kc4 * 4 + 2][2 * row] = v.z; Ad[kc4 * 4 + 2][2 * row + 1] = v.z;
            Ad[kc4 * 4 + 3][2 * row] = v.w; Ad[kc4 * 4 + 3][2 * row + 1] = v.w;
        }
#pragma unroll
        for (int i = 0; i < 2; ++i) {
            int f4 = i * 256 + tid;
            int k = f4 >> 4, c4 = f4 & 15;
            *(float4*)&Bs[k][c4 * 4] = *(const float4*)(W + (kk + k) * 64 + c4 * 4);
        }
        __syncthreads();
#pragma unroll
        for (int k = 0; k < 32; ++k) {
            const ulonglong2* ap = (const ulonglong2*)&Ad[k][ty * 16];
            ulonglong2 a01 = ap[0], a23 = ap[1], a45 = ap[2], a67 = ap[3];
            ulonglong2 bv = *(const ulonglong2*)&Bs[k][tx * 4];
            FMA_F32X2(acc[0][0], a01.x, bv.x, acc[0][0]);
            FMA_F32X2(acc[0][1], a01.x, bv.y, acc[0][1]);
            FMA_F32X2(acc[1][0], a01.y, bv.x, acc[1][0]);
            FMA_F32X2(acc[1][1], a01.y, bv.y, acc[1][1]);
            FMA_F32X2(acc[2][0], a23.x, bv.x, acc[2][0]);
            FMA_F32X2(acc[2][1], a23.x, bv.y, acc[2][1]);
            FMA_F32X2(acc[3][0], a23.y, bv.x, acc[3][0]);
            FMA_F32X2(acc[3][1], a23.y, bv.y, acc[3][1]);
            FMA_F32X2(acc[4][0], a45.x, bv.x, acc[4][0]);
            FMA_F32X2(acc[4][1], a45.x, bv.y, acc[4][1]);
            FMA_F32X2(acc[5][0], a45.y, bv.x, acc[5][0]);
            FMA_F32X2(acc[5][1], a45.y, bv.y, acc[5][1]);
            FMA_F32X2(acc[6][0], a67.x, bv.x, acc[6][0]);
            FMA_F32X2(acc[6][1], a67.x, bv.y, acc[6][1]);
            FMA_F32X2(acc[7][0], a67.y, bv.x, acc[7][0]);
            FMA_F32X2(acc[7][1], a67.y, bv.y, acc[7][1]);
        }
        __syncthreads();
    }
    float4 bb = *(const float4*)(b + tx * 4);
#pragma unroll
    for (int i = 0; i < 8; ++i) {
        int gr = r0 + ty * 8 + i;
        if (gr >= NU + NP) continue;
        float2 p0 = *(float2*)&acc[i][0];
        float2 p1 = *(float2*)&acc[i][1];
        float4 o = make_float4(p0.x + bb.x, p0.y + bb.y, p1.x + bb.z, p1.y + bb.w);
        float* dst = gr < NU ? g_hu + (size_t)gr * HID
                             : g_hp + (size_t)(gr - NU) * HID;
        *(float4*)(dst + tx * 4) = o;
    }
}

// ---------------- attention scalars, H read once per node ----------------
__global__ void k_att2() {
    int part = blockIdx.y;
    __shared__ float wf[4][HID * NH];
    int nz = part ? 2 : 4;
    int zsU[4] = {0, 1, 3, 4};
    int zsP[2] = {2, 5};
#pragma unroll
    for (int zi = 0; zi < 4; ++zi) {
        if (zi < nz) {
            int z = part ? zsP[zi] : zsU[zi];
            wf[zi][threadIdx.x] = g_wf[z][threadIdx.x];
        }
    }
    __syncthreads();
    int node = blockIdx.x * 256 + threadIdx.x;
    if (node >= NU) return;
    const float* hr = (part ? g_hp : g_hu) + (size_t)node * HID;
    float acc[4][4] = {};
#pragma unroll
    for (int c = 0; c < HID; c += 4) {
        float4 h4 = *(const float4*)(hr + c);
#pragma unroll
        for (int zi = 0; zi < 4; ++zi) {
            if (zi >= nz) break;
#pragma unroll
            for (int hh = 0; hh < 4; ++hh) {
                acc[zi][hh] += h4.x * wf[zi][(c + 0) * 4 + hh]
                             + h4.y * wf[zi][(c + 1) * 4 + hh]
                             + h4.z * wf[zi][(c + 2) * 4 + hh]
                             + h4.w * wf[zi][(c + 3) * 4 + hh];
            }
        }
    }
#pragma unroll
    for (int zi = 0; zi < 4; ++zi) {
        if (zi >= nz) break;
        int z = part ? zsP[zi] : zsU[zi];
        *(float4*)&g_a[z][node * 4] =
            make_float4(acc[zi][0], acc[zi][1], acc[zi][2], acc[zi][3]);
    }
}

// ---------------- batched CSR build ----------------
__global__ void k_zero3() {
    int i = blockIdx.x * 256 + threadIdx.x;
    if (i < 3 * NU) ((int*)g_cnt3)[i] = 0;
}
__global__ void k_hist3(const int* __restrict__ d0, const int* __restrict__ d1,
                        const int* __restrict__ d2, int E) {
    int t = blockIdx.y;
    const int* dst = t == 0 ? d0 : (t == 1 ? d1 : d2);
    int e = blockIdx.x * 256 + threadIdx.x;
    if (e < E) atomicAdd(&g_cnt3[t][dst[e]], 1);
}
__global__ void __launch_bounds__(1024) k_scan_a() {
    int t = blockIdx.y, chunk = blockIdx.x;
    __shared__ int warpsum[32];
    int tid = threadIdx.x;
    int lane = tid & 31, wid = tid >> 5;
    int idx0 = chunk * SCHUNK + tid * 4;
    int v[4];
    int s = 0;
#pragma unroll
    for (int q = 0; q < 4; ++q) {
        v[q] = (idx0 + q < NU) ? g_cnt3[t][idx0 + q] : 0;
        s += v[q];
    }
    int x = s;
#pragma unroll
    for (int o = 1; o < 32; o <<= 1) {
        int y = __shfl_up_sync(0xffffffffu, x, o);
        if (lane >= o) x += y;
    }
    if (lane == 31) warpsum[wid] = x;
    __syncthreads();
    if (wid == 0) {
        int w = warpsum[lane];
#pragma unroll
        for (int o = 1; o < 32; o <<= 1) {
            int y = __shfl_up_sync(0xffffffffu, w, o);
            if (lane >= o) w += y;
        }
        warpsum[lane] = w;
    }
    __syncthreads();
    int wprev = wid ? warpsum[wid - 1] : 0;
    int excl = wprev + (x - s);
#pragma unroll
    for (int q = 0; q < 4; ++q) {
        if (idx0 + q < NU) g_rp3[t][idx0 + q] = excl;
        excl += v[q];
    }
    if (tid == 0) g_csum[t][chunk] = warpsum[31];
}
__global__ void k_scan_b() {
    int w = threadIdx.x >> 5;
    int lane = threadIdx.x & 31;
    if (w >= 3) return;
    int val = lane < NCHUNK ? g_csum[w][lane] : 0;
    int x = val;
#pragma unroll
    for (int o = 1; o < 32; o <<= 1) {
        int y = __shfl_up_sync(0xffffffffu, x, o);
        if (lane >= o) x += y;
    }
    if (lane < NCHUNK) g_coff[w][lane] = x - val;
    if (lane == 31) g_rp3[w][NU] = x;
}
__global__ void __launch_bounds__(1024) k_scan_c() {
    int t = blockIdx.y, chunk = blockIdx.x;
    int off = g_coff[t][chunk];
    int idx0 = chunk * SCHUNK + threadIdx.x * 4;
#pragma unroll
    for (int q = 0; q < 4; ++q) {
        int i = idx0 + q;
        if (i < NU) {
            int r = g_rp3[t][i] + off;
            g_rp3[t][i] = r;
            g_cur3[t][i] = r;
        }
    }
}

// ---------------- fused scatter + logits: one pass over edges ----------------
__global__ void k_scatlog(const int* __restrict__ s0, const int* __restrict__ d0,
                          const int* __restrict__ s1, const int* __restrict__ d1,
                          const int* __restrict__ s2, const int* __restrict__ d2,
                          int E) {
    int t = blockIdx.y;
    const int* src = t == 0 ? s0 : (t == 1 ? s1 : s2);
    const int* dst = t == 0 ? d0 : (t == 1 ? d1 : d2);
    int e = blockIdx.x * 256 + threadIdx.x;
    if (e >= E) return;
    int s = src[e];
    int d = dst[e];
    int p = atomicAdd(&g_cur3[t][d], 1);
    float4 s4 = *(const float4*)&g_a[2 * t][s * 4];
    float4 d4 = *(const float4*)&g_a[2 * t + 1][d * 4];
    g_pe[t][p] = make_float4(lrelu(s4.x + d4.x), lrelu(s4.y + d4.y),
                             lrelu(s4.z + d4.z), lrelu(s4.w + d4.w));
    g_psrc[t][p] = s;
}

// ---------------- warp-per-dst softmax + aggregation in HID space ----------------
__global__ void __launch_bounds__(256) k_gat3() {
    int t = blockIdx.y;
    int d = (blockIdx.x * 256 + threadIdx.x) >> 5;
    int lane = threadIdx.x & 31;
    if (d >= NU) return;
    int beg = g_rp3[t][d], end = g_rp3[t][d + 1];
    const float* hsrc = (t == 1) ? g_hp : g_hu;
    const float4* pe = g_pe[t];
    const int* psrc = g_psrc[t];

    float m0 = -INFINITY, m1 = -INFINITY, m2 = -INFINITY, m3 = -INFINITY;
    for (int j = beg + lane; j < end; j += 32) {
        float4 ev = pe[j];
        m0 = fmaxf(m0, ev.x); m1 = fmaxf(m1, ev.y);
        m2 = fmaxf(m2, ev.z); m3 = fmaxf(m3, ev.w);
    }
#pragma unroll
    for (int o = 16; o; o >>= 1) {
        m0 = fmaxf(m0, __shfl_xor_sync(0xffffffffu, m0, o));
        m1 = fmaxf(m1, __shfl_xor_sync(0xffffffffu, m1, o));
        m2 = fmaxf(m2, __shfl_xor_sync(0xffffffffu, m2, o));
        m3 = fmaxf(m3, __shfl_xor_sync(0xffffffffu, m3, o));
    }
    float sm0 = 0.f, sm1 = 0.f, sm2 = 0.f, sm3 = 0.f;
    for (int j = beg + lane; j < end; j += 32) {
        float4 ev = pe[j];
        sm0 += __expf(ev.x - m0); sm1 += __expf(ev.y - m1);
        sm2 += __expf(ev.z - m2); sm3 += __expf(ev.w - m3);
    }
#pragma unroll
    for (int o = 16; o; o >>= 1) {
        sm0 += __shfl_xor_sync(0xffffffffu, sm0, o);
        sm1 += __shfl_xor_sync(0xffffffffu, sm1, o);
        sm2 += __shfl_xor_sync(0xffffffffu, sm2, o);
        sm3 += __shfl_xor_sync(0xffffffffu, sm3, o);
    }
    float i0 = 1.f / (sm0 + 1e-16f), i1 = 1.f / (sm1 + 1e-16f);
    float i2 = 1.f / (sm2 + 1e-16f), i3 = 1.f / (sm3 + 1e-16f);

    float acc[4][2] = {};
    int c0 = lane * 2;
    for (int base = beg; base < end; base += 32) {
        int j = base + lane;
        float4 a4 = make_float4(0.f, 0.f, 0.f, 0.f);
        int sj = 0;
        if (j < end) {
            float4 ev = pe[j];
            a4.x = __expf(ev.x - m0) * i0;
            a4.y = __expf(ev.y - m1) * i1;
            a4.z = __expf(ev.z - m2) * i2;
            a4.w = __expf(ev.w - m3) * i3;
            sj = psrc[j];
        }
        int cnt = min(32, end - base);
        for (int k = 0; k < cnt; ++k) {
            int sr  = __shfl_sync(0xffffffffu, sj, k);
            float ax = __shfl_sync(0xffffffffu, a4.x, k);
            float ay = __shfl_sync(0xffffffffu, a4.y, k);
            float az = __shfl_sync(0xffffffffu, a4.z, k);
            float aw = __shfl_sync(0xffffffffu, a4.w, k);
            float2 v = *(const float2*)&hsrc[(size_t)sr * HID + c0];
            acc[0][0] += ax * v.x; acc[0][1] += ax * v.y;
            acc[1][0] += ay * v.x; acc[1][1] += ay * v.y;
            acc[2][0] += az * v.x; acc[2][1] += az * v.y;
            acc[3][0] += aw * v.x; acc[3][1] += aw * v.y;
        }
    }
    float* zp = &g_z[t][(size_t)d * HH];
#pragma unroll
    for (int h = 0; h < 4; ++h)
        *(float2*)&zp[h * HID + c0] = make_float2(acc[h][0], acc[h][1]);
}

// ---------------- fused per-head GEMM + bias + ELU ----------------
// zi=0 (user):  elu(z0@lin0 + z1@lin1 + b_u2u + b_p2u) -> g_outU
// zi=1 (post):  elu(z2@lin2 + b_u2p)                   -> dout post region
__global__ void __launch_bounds__(256, 2) k_hg2(const float* __restrict__ l0,
                                                const float* __restrict__ l1,
                                                const float* __restrict__ l2,
                                                const float* __restrict__ b0,
                                                const float* __restrict__ b1,
                                                const float* __restrict__ b2,
                                                float* __restrict__ dout) {
    __shared__ float Ad[32][260];
    __shared__ float Bs[32][68];
    int zi = blockIdx.z, h = blockIdx.y;
    int tid = threadIdx.x;
    int r0 = blockIdx.x * 128;
    int tx = tid & 15, ty = tid >> 4;

    unsigned long long acc[8][2];
#pragma unroll
    for (int i = 0; i < 8; ++i) { acc[i][0] = 0ull; acc[i][1] = 0ull; }

    int ntt = zi == 0 ? 2 : 1;
    for (int tt = 0; tt < ntt; ++tt) {
        int t = zi == 0 ? tt : 2;
        const float* A = g_z[t];
        const float* lin = t == 0 ? l0 : (t == 1 ? l1 : l2);
        for (int kk = 0; kk < HID; kk += 32) {
#pragma unroll
            for (int i = 0; i < 4; ++i) {
                int f4 = i * 256 + tid;
                int row = f4 >> 3, kc4 = f4 & 7;
                int gr = r0 + row;
                float4 v = make_float4(0.f, 0.f, 0.f, 0.f);
                if (gr < NU)
                    v = *(const float4*)(A + (size_t)gr * HH + h * HID + kk + kc4 * 4);
                Ad[kc4 * 4 + 0][2 * row] = v.x; Ad[kc4 * 4 + 0][2 * row + 1] = v.x;
                Ad[kc4 * 4 + 1][2 * row] = v.y; Ad[kc4 * 4 + 1][2 * row + 1] = v.y;
                Ad[kc4 * 4 + 2][2 * row] = v.z; Ad[kc4 * 4 + 2][2 * row + 1] = v.z;
                Ad[kc4 * 4 + 3][2 * row] = v.w; Ad[kc4 * 4 + 3][2 * row + 1] = v.w;
            }
#pragma unroll
            for (int i = 0; i < 2; ++i) {
                int f4 = i * 256 + tid;
                int k = f4 >> 4, c4 = f4 & 15;
                *(float4*)&Bs[k][c4 * 4] =
                    *(const float4*)(lin + (size_t)(kk + k) * HH + h * HID + c4 * 4);
            }
            __syncthreads();
#pragma unroll
            for (int k = 0; k < 32; ++k) {
                const ulonglong2* ap = (const ulonglong2*)&Ad[k][ty * 16];
                ulonglong2 a01 = ap[0], a23 = ap[1], a45 = ap[2], a67 = ap[3];
                ulonglong2 bv = *(const ulonglong2*)&Bs[k][tx * 4];
                FMA_F32X2(acc[0][0], a01.x, bv.x, acc[0][0]);
                FMA_F32X2(acc[0][1], a01.x, bv.y, acc[0][1]);
                FMA_F32X2(acc[1][0], a01.y, bv.x, acc[1][0]);
                FMA_F32X2(acc[1][1], a01.y, bv.y, acc[1][1]);
                FMA_F32X2(acc[2][0], a23.x, bv.x, acc[2][0]);
                FMA_F32X2(acc[2][1], a23.x, bv.y, acc[2][1]);
                FMA_F32X2(acc[3][0], a23.y, bv.x, acc[3][0]);
                FMA_F32X2(acc[3][1], a23.y, bv.y, acc[3][1]);
                FMA_F32X2(acc[4][0], a45.x, bv.x, acc[4][0]);
                FMA_F32X2(acc[4][1], a45.x, bv.y, acc[4][1]);
                FMA_F32X2(acc[5][0], a45.y, bv.x, acc[5][0]);
                FMA_F32X2(acc[5][1], a45.y, bv.y, acc[5][1]);
                FMA_F32X2(acc[6][0], a67.x, bv.x, acc[6][0]);
                FMA_F32X2(acc[6][1], a67.x, bv.y, acc[6][1]);
                FMA_F32X2(acc[7][0], a67.y, bv.x, acc[7][0]);
                FMA_F32X2(acc[7][1], a67.y, bv.y, acc[7][1]);
            }
            __syncthreads();
        }
    }
    // bias + elu epilogue
    float4 bb;
    if (zi == 0) {
        float4 x1 = *(const float4*)(b0 + h * HID + tx * 4);
        float4 x2 = *(const float4*)(b1 + h * HID + tx * 4);
        bb = make_float4(x1.x + x2.x, x1.y + x2.y, x1.z + x2.z, x1.w + x2.w);
    } else {
        bb = *(const float4*)(b2 + h * HID + tx * 4);
    }
#pragma unroll
    for (int i = 0; i < 8; ++i) {
        int gr = r0 + ty * 8 + i;
        if (gr >= NU) continue;
        float2 p0 = *(float2*)&acc[i][0];
        float2 p1 = *(float2*)&acc[i][1];
        float4 o = make_float4(elu(p0.x + bb.x), elu(p0.y + bb.y),
                               elu(p1.x + bb.z), elu(p1.y + bb.w));
        if (zi == 0)
            *(float4*)&g_outU[(size_t)gr * HH + h * HID + tx * 4] = o;
        else
            *(float4*)(dout + (size_t)NU * OUTD + (size_t)gr * HH + h * HID + tx * 4) = o;
    }
}

// ---------------- user output (f32x2): g_outU @ W_out + b_out ----------------
__global__ void __launch_bounds__(256, 2) k_gout(const float* __restrict__ W,
                                                 const float* __restrict__ bo,
                                                 float* __restrict__ dout) {
    __shared__ float Ad[32][260];
    __shared__ float Bs[32][68];
    int tid = threadIdx.x;
    int r0 = blockIdx.x * 128;
    int tx = tid & 15, ty = tid >> 4;
    unsigned long long acc[8][2];
#pragma unroll
    for (int i = 0; i < 8; ++i) { acc[i][0] = 0ull; acc[i][1] = 0ull; }

    for (int kk = 0; kk < HH; kk += 32) {
#pragma unroll
        for (int i = 0; i < 4; ++i) {
            int f4 = i * 256 + tid;
            int row = f4 >> 3, kc4 = f4 & 7;
            int gr = r0 + row;
            float4 v = make_float4(0.f, 0.f, 0.f, 0.f);
            if (gr < NU)
                v = *(const float4*)&g_outU[(size_t)gr * HH + kk + kc4 * 4];
            Ad[kc4 * 4 + 0][2 * row] = v.x; Ad[kc4 * 4 + 0][2 * row + 1] = v.x;
            Ad[kc4 * 4 + 1][2 * row] = v.y; Ad[kc4 * 4 + 1][2 * row + 1] = v.y;
            Ad[kc4 * 4 + 2][2 * row] = v.z; Ad[kc4 * 4 + 2][2 * row + 1] = v.z;
            Ad[kc4 * 4 + 3][2 * row] = v.w; Ad[kc4 * 4 + 3][2 * row + 1] = v.w;
        }
#pragma unroll
        for (int i = 0; i < 2; ++i) {
            int f4 = i * 256 + tid;
            int k = f4 >> 4, c4 = f4 & 15;
            *(float4*)&Bs[k][c4 * 4] = *(const float4*)(W + (kk + k) * OUTD + c4 * 4);
        }
        __syncthreads();
#pragma unroll
        for (int k = 0; k < 32; ++k) {
            const ulonglong2* ap = (const ulonglong2*)&Ad[k][ty * 16];
            ulonglong2 a01 = ap[0], a23 = ap[1], a45 = ap[2], a67 = ap[3];
            ulonglong2 bv = *(const ulonglong2*)&Bs[k][tx * 4];
            FMA_F32X2(acc[0][0], a01.x, bv.x, acc[0][0]);
            FMA_F32X2(acc[0][1], a01.x, bv.y, acc[0][1]);
            FMA_F32X2(acc[1][0], a01.y, bv.x, acc[1][0]);
            FMA_F32X2(acc[1][1], a01.y, bv.y, acc[1][1]);
            FMA_F32X2(acc[2][0], a23.x, bv.x, acc[2][0]);
            FMA_F32X2(acc[2][1], a23.x, bv.y, acc[2][1]);
            FMA_F32X2(acc[3][0], a23.y, bv.x, acc[3][0]);
            FMA_F32X2(acc[3][1], a23.y, bv.y, acc[3][1]);
            FMA_F32X2(acc[4][0], a45.x, bv.x, acc[4][0]);
            FMA_F32X2(acc[4][1], a45.x, bv.y, acc[4][1]);
            FMA_F32X2(acc[5][0], a45.y, bv.x, acc[5][0]);
            FMA_F32X2(acc[5][1], a45.y, bv.y, acc[5][1]);
            FMA_F32X2(acc[6][0], a67.x, bv.x, acc[6][0]);
            FMA_F32X2(acc[6][1], a67.x, bv.y, acc[6][1]);
            FMA_F32X2(acc[7][0], a67.y, bv.x, acc[7][0]);
            FMA_F32X2(acc[7][1], a67.y, bv.y, acc[7][1]);
        }
        __syncthreads();
    }
    float4 bb = *(const float4*)(bo + tx * 4);
#pragma unroll
    for (int i = 0; i < 8; ++i) {
        int gr = r0 + ty * 8 + i;
        if (gr >= NU) continue;
        float2 p0 = *(float2*)&acc[i][0];
        float2 p1 = *(float2*)&acc[i][1];
        *(float4*)(dout + (size_t)gr * OUTD + tx * 4) =
            make_float4(p0.x + bb.x, p0.y + bb.y, p1.x + bb.z, p1.y + bb.w);
    }
}

// ---------------- launch ----------------
extern "C" void kernel_launch(void* const* d_in, const int* in_sizes, int n_in,
                              void* d_out, int out_size) {
    const float* x_user     = (const float*)d_in[0];
    const float* x_post     = (const float*)d_in[1];
    const int*   src_u2u    = (const int*)d_in[2];
    const int*   dst_u2u    = (const int*)d_in[3];
    const int*   src_p2u    = (const int*)d_in[4];
    const int*   dst_p2u    = (const int*)d_in[5];
    const int*   src_u2p    = (const int*)d_in[6];
    const int*   dst_u2p    = (const int*)d_in[7];
    const float* W_proj     = (const float*)d_in[8];
    const float* b_proj     = (const float*)d_in[9];
    const float* lin_u2u    = (const float*)d_in[10];
    const float* att_s_u2u  = (const float*)d_in[11];
    const float* att_d_u2u  = (const float*)d_in[12];
    const float* bias_u2u   = (const float*)d_in[13];
    const float* lin_p2u    = (const float*)d_in[14];
    const float* att_s_p2u  = (const float*)d_in[15];
    const float* att_d_p2u  = (const float*)d_in[16];
    const float* bias_p2u   = (const float*)d_in[17];
    const float* lin_u2p    = (const float*)d_in[18];
    const float* att_s_u2p  = (const float*)d_in[19];
    const float* att_d_u2p  = (const float*)d_in[20];
    const float* bias_u2p   = (const float*)d_in[21];
    const float* W_out      = (const float*)d_in[22];
    const float* b_out      = (const float*)d_in[23];
    float* out = (float*)d_out;
    int E = in_sizes[2];
    int gE = (E + 255) / 256;

    k_fold<<<6, 256>>>(lin_u2u, lin_p2u, lin_u2p,
                       att_s_u2u, att_d_u2u, att_s_p2u, att_d_p2u, att_s_u2p, att_d_u2p);
    k_zero3<<<(3 * NU + 255) / 256, 256>>>();
    k_hist3<<<dim3(gE, 3), 256>>>(dst_u2u, dst_p2u, dst_u2p, E);
    k_scan_a<<<dim3(NCHUNK, 3), 1024>>>();
    k_scan_b<<<1, 96>>>();
    k_scan_c<<<dim3(NCHUNK, 3), 1024>>>();

    k_proj<<<(NU + NP + 127) / 128, 256>>>(x_user, x_post, W_proj, b_proj);
    k_att2<<<dim3((NU + 255) / 256, 2), 256>>>();

    k_scatlog<<<dim3(gE, 3), 256>>>(src_u2u, dst_u2u, src_p2u, dst_p2u,
                                    src_u2p, dst_u2p, E);
    k_gat3<<<dim3((NU * 32 + 255) / 256, 3), 256>>>();
    k_hg2<<<dim3((NU + 127) / 128, NH, 2), 256>>>(lin_u2u, lin_p2u, lin_u2p,
                                                  bias_u2u, bias_p2u, bias_u2p, out);
    k_gout<<<(NU + 127) / 128, 256>>>(W_out, b_out, out);
}

// round 5
// speedup vs baseline: 1.7298x; 1.1337x over previous
#include <cuda_runtime.h>
#include <math.h>

#define NU 50000
#define NP 50000
#define NEMAX 400000
#define IND 128
#define HID 64
#define NH 4
#define HH 256   // HEADS*HID
#define OUTD 64
#define SCHUNK 4096
#define NCHUNK ((NU + SCHUNK - 1) / SCHUNK)   // 13

// f32x2 packed math (Blackwell sm_10x)
#define FMA_F32X2(d, a, b, c) \
    asm("fma.rn.f32x2 %0, %1, %2, %3;" : "=l"(d) : "l"(a), "l"(b), "l"(c))

// ---------------- scratch (static device globals; no allocation) ----------------
__device__ float  g_hu[NU * HID];
__device__ float  g_hp[NP * HID];
__device__ float  g_z[3][NU * HH];       // aggregated per-head features
__device__ float  g_a[6][NU * NH];       // folded attention scalars
__device__ float  g_wf[6][HID * NH];     // folded lin@att^T
__device__ int    g_psrc[3][NEMAX];      // src in CSR slot order
__device__ int    g_cnt3[3][NU];
__device__ int    g_rp3[3][NU + 1];
__device__ int    g_cur3[3][NU];
__device__ int    g_csum[3][NCHUNK];
__device__ int    g_coff[3][NCHUNK];
__device__ float  g_outU[NU * HH];       // elu(conv_u2u + conv_p2u + biases)

__device__ __forceinline__ float lrelu(float x) {
    return fmaxf(x, 0.f) + 0.2f * fminf(x, 0.f);
}
__device__ __forceinline__ float elu(float x) {
    return x > 0.f ? x : expm1f(x);
}

// ---------------- fold lin @ att^T into [64,4] per (edge-type, src/dst) ----------------
__global__ void k_fold(const float* __restrict__ l0, const float* __restrict__ l1,
                       const float* __restrict__ l2,
                       const float* __restrict__ a0, const float* __restrict__ a1,
                       const float* __restrict__ a2, const float* __restrict__ a3,
                       const float* __restrict__ a4, const float* __restrict__ a5) {
    int combo = blockIdx.x;  // 0..5
    const float* lin = combo < 2 ? l0 : (combo < 4 ? l1 : l2);
    const float* att = combo == 0 ? a0 : combo == 1 ? a1 : combo == 2 ? a2
                     : combo == 3 ? a3 : combo == 4 ? a4 : a5;
    int t = threadIdx.x;          // 256 threads = 64 cin x 4 heads
    int cin = t >> 2, h = t & 3;
    const float* lr = lin + cin * HH + h * HID;
    const float* ar = att + h * HID;
    float s = 0.f;
#pragma unroll 8
    for (int c = 0; c < HID; ++c) s += lr[c] * ar[c];
    g_wf[combo][cin * NH + h] = s;
}

// ---------------- projection (f32x2): [100000,128]@[128,64] + b -> g_hu / g_hp ----------------
__global__ void __launch_bounds__(256, 3) k_proj(const float* __restrict__ xu,
                                                 const float* __restrict__ xp,
                                                 const float* __restrict__ W,
                                                 const float* __restrict__ b) {
    __shared__ float Ad[32][260];   // duplicated A: [k][2*m]
    __shared__ float Bs[32][68];
    int tid = threadIdx.x;
    int r0 = blockIdx.x * 128;
    int tx = tid & 15, ty = tid >> 4;
    unsigned long long acc[8][2];
#pragma unroll
    for (int i = 0; i < 8; ++i) { acc[i][0] = 0ull; acc[i][1] = 0ull; }

    for (int kk = 0; kk < IND; kk += 32) {
#pragma unroll
        for (int i = 0; i < 4; ++i) {
            int f4 = i * 256 + tid;
            int row = f4 >> 3, kc4 = f4 & 7;
            int gr = r0 + row;
            float4 v = make_float4(0.f, 0.f, 0.f, 0.f);
            if (gr < NU + NP) {
                const float* srcp = gr < NU ? xu + (size_t)gr * IND
                                            : xp + (size_t)(gr - NU) * IND;
                v = *(const float4*)(srcp + kk + kc4 * 4);
            }
            Ad[kc4 * 4 + 0][2 * row] = v.x; Ad[kc4 * 4 + 0][2 * row + 1] = v.x;
            Ad[kc4 * 4 + 1][2 * row] = v.y; Ad[kc4 * 4 + 1][2 * row + 1] = v.y;
            Ad[kc4 * 4 + 2][2 * row] = v.z; Ad[kc4 * 4 + 2][2 * row + 1] = v.z;
            Ad[kc4 * 4 + 3][2 * row] = v.w; Ad[kc4 * 4 + 3][2 * row + 1] = v.w;
        }
#pragma unroll
        for (int i = 0; i < 2; ++i) {
            int f4 = i * 256 + tid;
            int k = f4 >> 4, c4 = f4 & 15;
            *(float4*)&Bs[k][c4 * 4] = *(const float4*)(W + (kk + k) * 64 + c4 * 4);
        }
        __syncthreads();
#pragma unroll
        for (int k = 0; k < 32; ++k) {
            const ulonglong2* ap = (const ulonglong2*)&Ad[k][ty * 16];
            ulonglong2 a01 = ap[0], a23 = ap[1], a45 = ap[2], a67 = ap[3];
            ulonglong2 bv = *(const ulonglong2*)&Bs[k][tx * 4];
            FMA_F32X2(acc[0][0], a01.x, bv.x, acc[0][0]);
            FMA_F32X2(acc[0][1], a01.x, bv.y, acc[0][1]);
            FMA_F32X2(acc[1][0], a01.y, bv.x, acc[1][0]);
            FMA_F32X2(acc[1][1], a01.y, bv.y, acc[1][1]);
            FMA_F32X2(acc[2][0], a23.x, bv.x, acc[2][0]);
            FMA_F32X2(acc[2][1], a23.x, bv.y, acc[2][1]);
            FMA_F32X2(acc[3][0], a23.y, bv.x, acc[3][0]);
            FMA_F32X2(acc[3][1], a23.y, bv.y, acc[3][1]);
            FMA_F32X2(acc[4][0], a45.x, bv.x, acc[4][0]);
            FMA_F32X2(acc[4][1], a45.x, bv.y, acc[4][1]);
            FMA_F32X2(acc[5][0], a45.y, bv.x, acc[5][0]);
            FMA_F32X2(acc[5][1], a45.y, bv.y, acc[5][1]);
            FMA_F32X2(acc[6][0], a67.x, bv.x, acc[6][0]);
            FMA_F32X2(acc[6][1], a67.x, bv.y, acc[6][1]);
            FMA_F32X2(acc[7][0], a67.y, bv.x, acc[7][0]);
            FMA_F32X2(acc[7][1], a67.y, bv.y, acc[7][1]);
        }
        __syncthreads();
    }
    float4 bb = *(const float4*)(b + tx * 4);
#pragma unroll
    for (int i = 0; i < 8; ++i) {
        int gr = r0 + ty * 8 + i;
        if (gr >= NU + NP) continue;
        float2 p0 = *(float2*)&acc[i][0];
        float2 p1 = *(float2*)&acc[i][1];
        float4 o = make_float4(p0.x + bb.x, p0.y + bb.y, p1.x + bb.z, p1.y + bb.w);
        float* dst = gr < NU ? g_hu + (size_t)gr * HID
                             : g_hp + (size_t)(gr - NU) * HID;
        *(float4*)(dst + tx * 4) = o;
    }
}

// ---------------- attention scalars, H read once per node ----------------
__global__ void k_att2() {
    int part = blockIdx.y;
    __shared__ float wf[4][HID * NH];
    int nz = part ? 2 : 4;
    int zsU[4] = {0, 1, 3, 4};
    int zsP[2] = {2, 5};
#pragma unroll
    for (int zi = 0; zi < 4; ++zi) {
        if (zi < nz) {
            int z = part ? zsP[zi] : zsU[zi];
            wf[zi][threadIdx.x] = g_wf[z][threadIdx.x];
        }
    }
    __syncthreads();
    int node = blockIdx.x * 256 + threadIdx.x;
    if (node >= NU) return;
    const float* hr = (part ? g_hp : g_hu) + (size_t)node * HID;
    float acc[4][4] = {};
#pragma unroll
    for (int c = 0; c < HID; c += 4) {
        float4 h4 = *(const float4*)(hr + c);
#pragma unroll
        for (int zi = 0; zi < 4; ++zi) {
            if (zi >= nz) break;
#pragma unroll
            for (int hh = 0; hh < 4; ++hh) {
                acc[zi][hh] += h4.x * wf[zi][(c + 0) * 4 + hh]
                             + h4.y * wf[zi][(c + 1) * 4 + hh]
                             + h4.z * wf[zi][(c + 2) * 4 + hh]
                             + h4.w * wf[zi][(c + 3) * 4 + hh];
            }
        }
    }
#pragma unroll
    for (int zi = 0; zi < 4; ++zi) {
        if (zi >= nz) break;
        int z = part ? zsP[zi] : zsU[zi];
        *(float4*)&g_a[z][node * 4] =
            make_float4(acc[zi][0], acc[zi][1], acc[zi][2], acc[zi][3]);
    }
}

// ---------------- batched CSR build ----------------
__global__ void k_zero3() {
    int i = blockIdx.x * 256 + threadIdx.x;
    if (i < 3 * NU) ((int*)g_cnt3)[i] = 0;
}
__global__ void k_hist3(const int* __restrict__ d0, const int* __restrict__ d1,
                        const int* __restrict__ d2, int E) {
    int t = blockIdx.y;
    const int* dst = t == 0 ? d0 : (t == 1 ? d1 : d2);
    int e = blockIdx.x * 256 + threadIdx.x;
    if (e < E) atomicAdd(&g_cnt3[t][dst[e]], 1);
}
__global__ void __launch_bounds__(1024) k_scan_a() {
    int t = blockIdx.y, chunk = blockIdx.x;
    __shared__ int warpsum[32];
    int tid = threadIdx.x;
    int lane = tid & 31, wid = tid >> 5;
    int idx0 = chunk * SCHUNK + tid * 4;
    int v[4];
    int s = 0;
#pragma unroll
    for (int q = 0; q < 4; ++q) {
        v[q] = (idx0 + q < NU) ? g_cnt3[t][idx0 + q] : 0;
        s += v[q];
    }
    int x = s;
#pragma unroll
    for (int o = 1; o < 32; o <<= 1) {
        int y = __shfl_up_sync(0xffffffffu, x, o);
        if (lane >= o) x += y;
    }
    if (lane == 31) warpsum[wid] = x;
    __syncthreads();
    if (wid == 0) {
        int w = warpsum[lane];
#pragma unroll
        for (int o = 1; o < 32; o <<= 1) {
            int y = __shfl_up_sync(0xffffffffu, w, o);
            if (lane >= o) w += y;
        }
        warpsum[lane] = w;
    }
    __syncthreads();
    int wprev = wid ? warpsum[wid - 1] : 0;
    int excl = wprev + (x - s);
#pragma unroll
    for (int q = 0; q < 4; ++q) {
        if (idx0 + q < NU) g_rp3[t][idx0 + q] = excl;
        excl += v[q];
    }
    if (tid == 0) g_csum[t][chunk] = warpsum[31];
}
__global__ void k_scan_b() {
    int w = threadIdx.x >> 5;
    int lane = threadIdx.x & 31;
    if (w >= 3) return;
    int val = lane < NCHUNK ? g_csum[w][lane] : 0;
    int x = val;
#pragma unroll
    for (int o = 1; o < 32; o <<= 1) {
        int y = __shfl_up_sync(0xffffffffu, x, o);
        if (lane >= o) x += y;
    }
    if (lane < NCHUNK) g_coff[w][lane] = x - val;
    if (lane == 31) g_rp3[w][NU] = x;
}
__global__ void __launch_bounds__(1024) k_scan_c() {
    int t = blockIdx.y, chunk = blockIdx.x;
    int off = g_coff[t][chunk];
    int idx0 = chunk * SCHUNK + threadIdx.x * 4;
#pragma unroll
    for (int q = 0; q < 4; ++q) {
        int i = idx0 + q;
        if (i < NU) {
            int r = g_rp3[t][i] + off;
            g_rp3[t][i] = r;
            g_cur3[t][i] = r;
        }
    }
}

// ---------------- scatter src into CSR slots (no logits materialized) ----------------
__global__ void k_scat(const int* __restrict__ s0, const int* __restrict__ d0,
                       const int* __restrict__ s1, const int* __restrict__ d1,
                       const int* __restrict__ s2, const int* __restrict__ d2,
                       int E) {
    int t = blockIdx.y;
    const int* src = t == 0 ? s0 : (t == 1 ? s1 : s2);
    const int* dst = t == 0 ? d0 : (t == 1 ? d1 : d2);
    int e = blockIdx.x * 256 + threadIdx.x;
    if (e >= E) return;
    int p = atomicAdd(&g_cur3[t][dst[e]], 1);
    g_psrc[t][p] = src[e];
}

// ---------------- warp-per-dst: logits + softmax + HID-space aggregation ----------------
__global__ void __launch_bounds__(256) k_gat4() {
    int t = blockIdx.y;
    int d = (blockIdx.x * 256 + threadIdx.x) >> 5;
    int lane = threadIdx.x & 31;
    if (d >= NU) return;
    int beg = g_rp3[t][d], end = g_rp3[t][d + 1];
    int deg = end - beg;
    const float* hsrc = (t == 1) ? g_hp : g_hu;
    const int* psrc = g_psrc[t];
    const float* aS = g_a[2 * t];
    float4 ad = *(const float4*)&g_a[2 * t + 1][d * 4];
    int c0 = lane * 2;
    float* zp = &g_z[t][(size_t)d * HH];

    if (deg == 0) {
#pragma unroll
        for (int h = 0; h < 4; ++h)
            *(float2*)&zp[h * HID + c0] = make_float2(0.f, 0.f);
        return;
    }

    int h = lane >> 3;
    float acc[4][2] = {};

    if (deg <= 32) {
        // ---- register-cached fast path (one gather per edge) ----
        bool valid = lane < deg;
        int sj = valid ? psrc[beg + lane] : 0;
        float4 ev = make_float4(-INFINITY, -INFINITY, -INFINITY, -INFINITY);
        if (valid) {
            float4 s4 = *(const float4*)&aS[sj * 4];
            ev = make_float4(lrelu(s4.x + ad.x), lrelu(s4.y + ad.y),
                             lrelu(s4.z + ad.z), lrelu(s4.w + ad.w));
        }
        float m0 = ev.x, m1 = ev.y, m2 = ev.z, m3 = ev.w;
#pragma unroll
        for (int o = 16; o; o >>= 1) {
            m0 = fmaxf(m0, __shfl_xor_sync(0xffffffffu, m0, o));
            m1 = fmaxf(m1, __shfl_xor_sync(0xffffffffu, m1, o));
            m2 = fmaxf(m2, __shfl_xor_sync(0xffffffffu, m2, o));
            m3 = fmaxf(m3, __shfl_xor_sync(0xffffffffu, m3, o));
        }
        float e0 = valid ? __expf(ev.x - m0) : 0.f;
        float e1 = valid ? __expf(ev.y - m1) : 0.f;
        float e2 = valid ? __expf(ev.z - m2) : 0.f;
        float e3 = valid ? __expf(ev.w - m3) : 0.f;
        float s0 = e0, s1 = e1, s2 = e2, s3 = e3;
#pragma unroll
        for (int o = 16; o; o >>= 1) {
            s0 += __shfl_xor_sync(0xffffffffu, s0, o);
            s1 += __shfl_xor_sync(0xffffffffu, s1, o);
            s2 += __shfl_xor_sync(0xffffffffu, s2, o);
            s3 += __shfl_xor_sync(0xffffffffu, s3, o);
        }
        float ax = e0 / (s0 + 1e-16f);
        float ay = e1 / (s1 + 1e-16f);
        float az = e2 / (s2 + 1e-16f);
        float aw = e3 / (s3 + 1e-16f);
        for (int k = 0; k < deg; ++k) {
            int sr  = __shfl_sync(0xffffffffu, sj, k);
            float bx = __shfl_sync(0xffffffffu, ax, k);
            float by = __shfl_sync(0xffffffffu, ay, k);
            float bz = __shfl_sync(0xffffffffu, az, k);
            float bw = __shfl_sync(0xffffffffu, aw, k);
            float al = h == 0 ? bx : h == 1 ? by : h == 2 ? bz : bw;
            float2 v = *(const float2*)&hsrc[(size_t)sr * HID + c0];
            acc[0][0] += bx * v.x; acc[0][1] += bx * v.y;
            acc[1][0] += by * v.x; acc[1][1] += by * v.y;
            acc[2][0] += bz * v.x; acc[2][1] += bz * v.y;
            acc[3][0] += bw * v.x; acc[3][1] += bw * v.y;
            (void)al;
        }
    } else {
        // ---- streaming fallback (deg > 32, vanishingly rare) ----
        float m0 = -INFINITY, m1 = -INFINITY, m2 = -INFINITY, m3 = -INFINITY;
        for (int j = beg + lane; j < end; j += 32) {
            float4 s4 = *(const float4*)&aS[psrc[j] * 4];
            m0 = fmaxf(m0, lrelu(s4.x + ad.x));
            m1 = fmaxf(m1, lrelu(s4.y + ad.y));
            m2 = fmaxf(m2, lrelu(s4.z + ad.z));
            m3 = fmaxf(m3, lrelu(s4.w + ad.w));
        }
#pragma unroll
        for (int o = 16; o; o >>= 1) {
            m0 = fmaxf(m0, __shfl_xor_sync(0xffffffffu, m0, o));
            m1 = fmaxf(m1, __shfl_xor_sync(0xffffffffu, m1, o));
            m2 = fmaxf(m2, __shfl_xor_sync(0xffffffffu, m2, o));
            m3 = fmaxf(m3, __shfl_xor_sync(0xffffffffu, m3, o));
        }
        float s0 = 0.f, s1 = 0.f, s2 = 0.f, s3 = 0.f;
        for (int j = beg + lane; j < end; j += 32) {
            float4 s4 = *(const float4*)&aS[psrc[j] * 4];
            s0 += __expf(lrelu(s4.x + ad.x) - m0);
            s1 += __expf(lrelu(s4.y + ad.y) - m1);
            s2 += __expf(lrelu(s4.z + ad.z) - m2);
            s3 += __expf(lrelu(s4.w + ad.w) - m3);
        }
#pragma unroll
        for (int o = 16; o; o >>= 1) {
            s0 += __shfl_xor_sync(0xffffffffu, s0, o);
            s1 += __shfl_xor_sync(0xffffffffu, s1, o);
            s2 += __shfl_xor_sync(0xffffffffu, s2, o);
            s3 += __shfl_xor_sync(0xffffffffu, s3, o);
        }
        float i0 = 1.f / (s0 + 1e-16f), i1 = 1.f / (s1 + 1e-16f);
        float i2 = 1.f / (s2 + 1e-16f), i3 = 1.f / (s3 + 1e-16f);
        for (int base = beg; base < end; base += 32) {
            int j = base + lane;
            float ax = 0.f, ay = 0.f, az = 0.f, aw = 0.f;
            int sj = 0;
            if (j < end) {
                sj = psrc[j];
                float4 s4 = *(const float4*)&aS[sj * 4];
                ax = __expf(lrelu(s4.x + ad.x) - m0) * i0;
                ay = __expf(lrelu(s4.y + ad.y) - m1) * i1;
                az = __expf(lrelu(s4.z + ad.z) - m2) * i2;
                aw = __expf(lrelu(s4.w + ad.w) - m3) * i3;
            }
            int cnt = min(32, end - base);
            for (int k = 0; k < cnt; ++k) {
                int sr  = __shfl_sync(0xffffffffu, sj, k);
                float bx = __shfl_sync(0xffffffffu, ax, k);
                float by = __shfl_sync(0xffffffffu, ay, k);
                float bz = __shfl_sync(0xffffffffu, az, k);
                float bw = __shfl_sync(0xffffffffu, aw, k);
                float2 v = *(const float2*)&hsrc[(size_t)sr * HID + c0];
                acc[0][0] += bx * v.x; acc[0][1] += bx * v.y;
                acc[1][0] += by * v.x; acc[1][1] += by * v.y;
                acc[2][0] += bz * v.x; acc[2][1] += bz * v.y;
                acc[3][0] += bw * v.x; acc[3][1] += bw * v.y;
            }
        }
    }
#pragma unroll
    for (int hh = 0; hh < 4; ++hh)
        *(float2*)&zp[hh * HID + c0] = make_float2(acc[hh][0], acc[hh][1]);
}

// ---------------- fused per-head GEMM + bias + ELU ----------------
__global__ void __launch_bounds__(256, 3) k_hg2(const float* __restrict__ l0,
                                                const float* __restrict__ l1,
                                                const float* __restrict__ l2,
                                                const float* __restrict__ b0,
                                                const float* __restrict__ b1,
                                                const float* __restrict__ b2,
                                                float* __restrict__ dout) {
    __shared__ float Ad[32][260];
    __shared__ float Bs[32][68];
    int zi = blockIdx.z, h = blockIdx.y;
    int tid = threadIdx.x;
    int r0 = blockIdx.x * 128;
    int tx = tid & 15, ty = tid >> 4;

    unsigned long long acc[8][2];
#pragma unroll
    for (int i = 0; i < 8; ++i) { acc[i][0] = 0ull; acc[i][1] = 0ull; }

    int ntt = zi == 0 ? 2 : 1;
    for (int tt = 0; tt < ntt; ++tt) {
        int t = zi == 0 ? tt : 2;
        const float* A = g_z[t];
        const float* lin = t == 0 ? l0 : (t == 1 ? l1 : l2);
        for (int kk = 0; kk < HID; kk += 32) {
#pragma unroll
            for (int i = 0; i < 4; ++i) {
                int f4 = i * 256 + tid;
                int row = f4 >> 3, kc4 = f4 & 7;
                int gr = r0 + row;
                float4 v = make_float4(0.f, 0.f, 0.f, 0.f);
                if (gr < NU)
                    v = *(const float4*)(A + (size_t)gr * HH + h * HID + kk + kc4 * 4);
                Ad[kc4 * 4 + 0][2 * row] = v.x; Ad[kc4 * 4 + 0][2 * row + 1] = v.x;
                Ad[kc4 * 4 + 1][2 * row] = v.y; Ad[kc4 * 4 + 1][2 * row + 1] = v.y;
                Ad[kc4 * 4 + 2][2 * row] = v.z; Ad[kc4 * 4 + 2][2 * row + 1] = v.z;
                Ad[kc4 * 4 + 3][2 * row] = v.w; Ad[kc4 * 4 + 3][2 * row + 1] = v.w;
            }
#pragma unroll
            for (int i = 0; i < 2; ++i) {
                int f4 = i * 256 + tid;
                int k = f4 >> 4, c4 = f4 & 15;
                *(float4*)&Bs[k][c4 * 4] =
                    *(const float4*)(lin + (size_t)(kk + k) * HH + h * HID + c4 * 4);
            }
            __syncthreads();
#pragma unroll
            for (int k = 0; k < 32; ++k) {
                const ulonglong2* ap = (const ulonglong2*)&Ad[k][ty * 16];
                ulonglong2 a01 = ap[0], a23 = ap[1], a45 = ap[2], a67 = ap[3];
                ulonglong2 bv = *(const ulonglong2*)&Bs[k][tx * 4];
                FMA_F32X2(acc[0][0], a01.x, bv.x, acc[0][0]);
                FMA_F32X2(acc[0][1], a01.x, bv.y, acc[0][1]);
                FMA_F32X2(acc[1][0], a01.y, bv.x, acc[1][0]);
                FMA_F32X2(acc[1][1], a01.y, bv.y, acc[1][1]);
                FMA_F32X2(acc[2][0], a23.x, bv.x, acc[2][0]);
                FMA_F32X2(acc[2][1], a23.x, bv.y, acc[2][1]);
                FMA_F32X2(acc[3][0], a23.y, bv.x, acc[3][0]);
                FMA_F32X2(acc[3][1], a23.y, bv.y, acc[3][1]);
                FMA_F32X2(acc[4][0], a45.x, bv.x, acc[4][0]);
                FMA_F32X2(acc[4][1], a45.x, bv.y, acc[4][1]);
                FMA_F32X2(acc[5][0], a45.y, bv.x, acc[5][0]);
                FMA_F32X2(acc[5][1], a45.y, bv.y, acc[5][1]);
                FMA_F32X2(acc[6][0], a67.x, bv.x, acc[6][0]);
                FMA_F32X2(acc[6][1], a67.x, bv.y, acc[6][1]);
                FMA_F32X2(acc[7][0], a67.y, bv.x, acc[7][0]);
                FMA_F32X2(acc[7][1], a67.y, bv.y, acc[7][1]);
            }
            __syncthreads();
        }
    }
    float4 bb;
    if (zi == 0) {
        float4 x1 = *(const float4*)(b0 + h * HID + tx * 4);
        float4 x2 = *(const float4*)(b1 + h * HID + tx * 4);
        bb = make_float4(x1.x + x2.x, x1.y + x2.y, x1.z + x2.z, x1.w + x2.w);
    } else {
        bb = *(const float4*)(b2 + h * HID + tx * 4);
    }
#pragma unroll
    for (int i = 0; i < 8; ++i) {
        int gr = r0 + ty * 8 + i;
        if (gr >= NU) continue;
        float2 p0 = *(float2*)&acc[i][0];
        float2 p1 = *(float2*)&acc[i][1];
        float4 o = make_float4(elu(p0.x + bb.x), elu(p0.y + bb.y),
                               elu(p1.x + bb.z), elu(p1.y + bb.w));
        if (zi == 0)
            *(float4*)&g_outU[(size_t)gr * HH + h * HID + tx * 4] = o;
        else
            *(float4*)(dout + (size_t)NU * OUTD + (size_t)gr * HH + h * HID + tx * 4) = o;
    }
}

// ---------------- user output (f32x2): g_outU @ W_out + b_out ----------------
__global__ void __launch_bounds__(256, 3) k_gout(const float* __restrict__ W,
                                                 const float* __restrict__ bo,
                                                 float* __restrict__ dout) {
    __shared__ float Ad[32][260];
    __shared__ float Bs[32][68];
    int tid = threadIdx.x;
    int r0 = blockIdx.x * 128;
    int tx = tid & 15, ty = tid >> 4;
    unsigned long long acc[8][2];
#pragma unroll
    for (int i = 0; i < 8; ++i) { acc[i][0] = 0ull; acc[i][1] = 0ull; }

    for (int kk = 0; kk < HH; kk += 32) {
#pragma unroll
        for (int i = 0; i < 4; ++i) {
            int f4 = i * 256 + tid;
            int row = f4 >> 3, kc4 = f4 & 7;
            int gr = r0 + row;
            float4 v = make_float4(0.f, 0.f, 0.f, 0.f);
            if (gr < NU)
                v = *(const float4*)&g_outU[(size_t)gr * HH + kk + kc4 * 4];
            Ad[kc4 * 4 + 0][2 * row] = v.x; Ad[kc4 * 4 + 0][2 * row + 1] = v.x;
            Ad[kc4 * 4 + 1][2 * row] = v.y; Ad[kc4 * 4 + 1][2 * row + 1] = v.y;
            Ad[kc4 * 4 + 2][2 * row] = v.z; Ad[kc4 * 4 + 2][2 * row + 1] = v.z;
            Ad[kc4 * 4 + 3][2 * row] = v.w; Ad[kc4 * 4 + 3][2 * row + 1] = v.w;
        }
#pragma unroll
        for (int i = 0; i < 2; ++i) {
            int f4 = i * 256 + tid;
            int k = f4 >> 4, c4 = f4 & 15;
            *(float4*)&Bs[k][c4 * 4] = *(const float4*)(W + (kk + k) * OUTD + c4 * 4);
        }
        __syncthreads();
#pragma unroll
        for (int k = 0; k < 32; ++k) {
            const ulonglong2* ap = (const ulonglong2*)&Ad[k][ty * 16];
            ulonglong2 a01 = ap[0], a23 = ap[1], a45 = ap[2], a67 = ap[3];
            ulonglong2 bv = *(const ulonglong2*)&Bs[k][tx * 4];
            FMA_F32X2(acc[0][0], a01.x, bv.x, acc[0][0]);
            FMA_F32X2(acc[0][1], a01.x, bv.y, acc[0][1]);
            FMA_F32X2(acc[1][0], a01.y, bv.x, acc[1][0]);
            FMA_F32X2(acc[1][1], a01.y, bv.y, acc[1][1]);
            FMA_F32X2(acc[2][0], a23.x, bv.x, acc[2][0]);
            FMA_F32X2(acc[2][1], a23.x, bv.y, acc[2][1]);
            FMA_F32X2(acc[3][0], a23.y, bv.x, acc[3][0]);
            FMA_F32X2(acc[3][1], a23.y, bv.y, acc[3][1]);
            FMA_F32X2(acc[4][0], a45.x, bv.x, acc[4][0]);
            FMA_F32X2(acc[4][1], a45.x, bv.y, acc[4][1]);
            FMA_F32X2(acc[5][0], a45.y, bv.x, acc[5][0]);
            FMA_F32X2(acc[5][1], a45.y, bv.y, acc[5][1]);
            FMA_F32X2(acc[6][0], a67.x, bv.x, acc[6][0]);
            FMA_F32X2(acc[6][1], a67.x, bv.y, acc[6][1]);
            FMA_F32X2(acc[7][0], a67.y, bv.x, acc[7][0]);
            FMA_F32X2(acc[7][1], a67.y, bv.y, acc[7][1]);
        }
        __syncthreads();
    }
    float4 bb = *(const float4*)(bo + tx * 4);
#pragma unroll
    for (int i = 0; i < 8; ++i) {
        int gr = r0 + ty * 8 + i;
        if (gr >= NU) continue;
        float2 p0 = *(float2*)&acc[i][0];
        float2 p1 = *(float2*)&acc[i][1];
        *(float4*)(dout + (size_t)gr * OUTD + tx * 4) =
            make_float4(p0.x + bb.x, p0.y + bb.y, p1.x + bb.z, p1.y + bb.w);
    }
}

// ---------------- launch ----------------
extern "C" void kernel_launch(void* const* d_in, const int* in_sizes, int n_in,
                              void* d_out, int out_size) {
    const float* x_user     = (const float*)d_in[0];
    const float* x_post     = (const float*)d_in[1];
    const int*   src_u2u    = (const int*)d_in[2];
    const int*   dst_u2u    = (const int*)d_in[3];
    const int*   src_p2u    = (const int*)d_in[4];
    const int*   dst_p2u    = (const int*)d_in[5];
    const int*   src_u2p    = (const int*)d_in[6];
    const int*   dst_u2p    = (const int*)d_in[7];
    const float* W_proj     = (const float*)d_in[8];
    const float* b_proj     = (const float*)d_in[9];
    const float* lin_u2u    = (const float*)d_in[10];
    const float* att_s_u2u  = (const float*)d_in[11];
    const float* att_d_u2u  = (const float*)d_in[12];
    const float* bias_u2u   = (const float*)d_in[13];
    const float* lin_p2u    = (const float*)d_in[14];
    const float* att_s_p2u  = (const float*)d_in[15];
    const float* att_d_p2u  = (const float*)d_in[16];
    const float* bias_p2u   = (const float*)d_in[17];
    const float* lin_u2p    = (const float*)d_in[18];
    const float* att_s_u2p  = (const float*)d_in[19];
    const float* att_d_u2p  = (const float*)d_in[20];
    const float* bias_u2p   = (const float*)d_in[21];
    const float* W_out      = (const float*)d_in[22];
    const float* b_out      = (const float*)d_in[23];
    float* out = (float*)d_out;
    int E = in_sizes[2];
    int gE = (E + 255) / 256;

    // launch order chosen so index 5 (ncu -s 5 -c 1) is k_proj
    k_fold<<<6, 256>>>(lin_u2u, lin_p2u, lin_u2p,                       // 0
                       att_s_u2u, att_d_u2u, att_s_p2u, att_d_p2u, att_s_u2p, att_d_u2p);
    k_zero3<<<(3 * NU + 255) / 256, 256>>>();                           // 1
    k_hist3<<<dim3(gE, 3), 256>>>(dst_u2u, dst_p2u, dst_u2p, E);        // 2
    k_scan_a<<<dim3(NCHUNK, 3), 1024>>>();                              // 3
    k_scan_b<<<1, 96>>>();                                              // 4
    k_proj<<<(NU + NP + 127) / 128, 256>>>(x_user, x_post, W_proj, b_proj); // 5 (profiled)
    k_scan_c<<<dim3(NCHUNK, 3), 1024>>>();                              // 6
    k_att2<<<dim3((NU + 255) / 256, 2), 256>>>();                       // 7
    k_scat<<<dim3(gE, 3), 256>>>(src_u2u, dst_u2u, src_p2u, dst_p2u,    // 8
                                 src_u2p, dst_u2p, E);
    k_gat4<<<dim3((NU * 32 + 255) / 256, 3), 256>>>();                  // 9
    k_hg2<<<dim3((NU + 127) / 128, NH, 2), 256>>>(lin_u2u, lin_p2u, lin_u2p,  // 10
                                                  bias_u2u, bias_p2u, bias_u2p, out);
    k_gout<<<(NU + 127) / 128, 256>>>(W_out, b_out, out);               // 11
}